// round 6
// baseline (speedup 1.0000x reference)
#include <cuda_runtime.h>
#include <math.h>
#include <stdint.h>

#define Bsz   2048
#define Ssz   23
#define Esz   768
#define REDsz 256
#define Hsz   8
#define DHsz  32
#define NLAB  25
#define Mrows (Bsz*Ssz)   // 47104 = 368*128

// ---------------- scratch (allocation-free) ----------------
__device__ float g_h1 [(size_t)Mrows*384];
__device__ float g_h2 [(size_t)Mrows*256];
__device__ float g_red[(size_t)Mrows*256];
__device__ float g_q  [(size_t)Mrows*256];
__device__ float g_k  [(size_t)Mrows*256];
__device__ float g_v  [(size_t)Mrows*256];
__device__ float g_ctx[(size_t)Mrows*256];
__device__ float g_upd[(size_t)Mrows*256];
__device__ unsigned char g_use[Mrows];
__device__ float g_acc;

__device__ __forceinline__ float gelu_f(float x) {
    return 0.5f * x * (1.0f + erff(x * 0.70710678118654752440f));
}

union F2U { unsigned long long u; float2 f; };

#define FFMA2(acc_, a_, b_) \
    asm("fma.rn.f32x2 %0, %1, %2, %0;" : "+l"(acc_) : "l"(a_), "l"(b_))

#define LDS128_U64(r0_, r1_, addr_) \
    asm volatile("ld.shared.v2.b64 {%0,%1}, [%2];" : "=l"(r0_), "=l"(r1_) : "r"(addr_))

// ---------------- tiled SGEMM (FFMA2): C = act(A @ W^T + bias) ----------------
// BM=BN=128, BK=16, 256 threads, 8x8 microtile, split-quad layout.
// A tile stored DUPLICATED in smem ([a,a] pairs) so splat pairs come from LDS.128.
// Double-buffered smem, one __syncthreads per k-tile.
// MODE 0: plain. MODE 1: A gathered from cls/missing by mask.
// MODE 2: epilogue select vs g_red (N=256). MODE 3: fused QKV (grid.x=6).
template<int ACT, int MODE>
__global__ void __launch_bounds__(256, 2) gemm128_k(
    const float* __restrict__ A,
    const float* __restrict__ Wa, const float* __restrict__ Wb, const float* __restrict__ Wc,
    const float* __restrict__ ba, const float* __restrict__ bb, const float* __restrict__ bc,
    float* __restrict__ Ca, float* __restrict__ Cb, float* __restrict__ Cc,
    int N, int K,
    const float* __restrict__ cls, const float* __restrict__ miss,
    const int* __restrict__ mask)
{
    __shared__ float As2[2][16][256];   // duplicated columns: [2m]=[2m+1]=a[m]
    __shared__ float Bs [2][16][128];

    const int tid = threadIdx.x;
    const int bm = blockIdx.y * 128;

    const float* W; const float* bias; float* C; int bn;
    if (MODE == 3) {
        int sel = blockIdx.x >> 1;
        W    = sel == 0 ? Wa : sel == 1 ? Wb : Wc;
        bias = sel == 0 ? ba : sel == 1 ? bb : bc;
        C    = sel == 0 ? Ca : sel == 1 ? Cb : Cc;
        bn = (blockIdx.x & 1) * 128;
    } else {
        W = Wa; bias = ba; C = Ca;
        bn = blockIdx.x * 128;
    }

    const int lrow = tid >> 1;           // 0..127
    const int lk   = (tid & 1) << 3;     // 0 or 8

    const float* Arow;
    if (MODE == 1) {
        int r = bm + lrow;
        Arow = (mask[r] > 0) ? (cls + (size_t)r * Esz)
                             : (miss + (size_t)(r % Ssz) * Esz);
    } else {
        Arow = A + (size_t)(bm + lrow) * K;
    }
    const float* Brow = W + (size_t)(bn + lrow) * K;

    const int tx = tid & 15;             // 0..15
    const int ty = tid >> 4;             // 0..15
    const int mA = ty << 2;              // m-quad base (second at +64)
    const int nA = tx << 2;              // n-quad base (second at +64)

    // shared addresses (byte offsets within shared window)
    uint32_t sA_base, sB_base;
    {
        uint32_t a32, b32;
        asm("{ .reg .u64 t; cvta.to.shared.u64 t, %1; cvt.u32.u64 %0, t; }"
            : "=r"(a32) : "l"(&As2[0][0][0]));
        asm("{ .reg .u64 t; cvta.to.shared.u64 t, %1; cvt.u32.u64 %0, t; }"
            : "=r"(b32) : "l"(&Bs[0][0][0]));
        sA_base = a32; sB_base = b32;
    }
    const uint32_t aRd = sA_base + (uint32_t)(2 * mA) * 4u;  // read base (buf 0)
    const uint32_t bRd = sB_base + (uint32_t)nA * 4u;

    unsigned long long acc[8][4] = {};
    float4 pa0, pa1, pb0, pb1;

    // prefetch tile 0
    pa0 = *reinterpret_cast<const float4*>(Arow + lk);
    pa1 = *reinterpret_cast<const float4*>(Arow + lk + 4);
    pb0 = *reinterpret_cast<const float4*>(Brow + lk);
    pb1 = *reinterpret_cast<const float4*>(Brow + lk + 4);

    // store tile 0 into buffer 0 (k-row stride = 256 floats)
    {
        float* aS = &As2[0][lk][2 * lrow];
        *reinterpret_cast<float2*>(aS + 0*256) = make_float2(pa0.x, pa0.x);
        *reinterpret_cast<float2*>(aS + 1*256) = make_float2(pa0.y, pa0.y);
        *reinterpret_cast<float2*>(aS + 2*256) = make_float2(pa0.z, pa0.z);
        *reinterpret_cast<float2*>(aS + 3*256) = make_float2(pa0.w, pa0.w);
        *reinterpret_cast<float2*>(aS + 4*256) = make_float2(pa1.x, pa1.x);
        *reinterpret_cast<float2*>(aS + 5*256) = make_float2(pa1.y, pa1.y);
        *reinterpret_cast<float2*>(aS + 6*256) = make_float2(pa1.z, pa1.z);
        *reinterpret_cast<float2*>(aS + 7*256) = make_float2(pa1.w, pa1.w);
        Bs[0][lk+0][lrow]=pb0.x; Bs[0][lk+1][lrow]=pb0.y; Bs[0][lk+2][lrow]=pb0.z; Bs[0][lk+3][lrow]=pb0.w;
        Bs[0][lk+4][lrow]=pb1.x; Bs[0][lk+5][lrow]=pb1.y; Bs[0][lk+6][lrow]=pb1.z; Bs[0][lk+7][lrow]=pb1.w;
    }
    __syncthreads();

    const int nIter = K >> 4;
    for (int it = 0; it < nIter; it++) {
        const int buf = it & 1;
        const bool more = (it + 1) < nIter;

        // prefetch next tile
        if (more) {
            int k0 = (it + 1) << 4;
            pa0 = *reinterpret_cast<const float4*>(Arow + k0 + lk);
            pa1 = *reinterpret_cast<const float4*>(Arow + k0 + lk + 4);
            pb0 = *reinterpret_cast<const float4*>(Brow + k0 + lk);
            pb1 = *reinterpret_cast<const float4*>(Brow + k0 + lk + 4);
        }

        const uint32_t aA = aRd + (uint32_t)buf * 16384u;
        const uint32_t bA = bRd + (uint32_t)buf * 8192u;

        #pragma unroll
        for (int kk = 0; kk < 16; kk++) {
            unsigned long long ap0,ap1,ap2,ap3,ap4,ap5,ap6,ap7, bp0,bp1,bp2,bp3;
            LDS128_U64(ap0, ap1, aA + kk*1024u);
            LDS128_U64(ap2, ap3, aA + kk*1024u + 16u);
            LDS128_U64(ap4, ap5, aA + kk*1024u + 512u);
            LDS128_U64(ap6, ap7, aA + kk*1024u + 528u);
            LDS128_U64(bp0, bp1, bA + kk*512u);
            LDS128_U64(bp2, bp3, bA + kk*512u + 256u);
            FFMA2(acc[0][0], ap0, bp0); FFMA2(acc[0][1], ap0, bp1);
            FFMA2(acc[0][2], ap0, bp2); FFMA2(acc[0][3], ap0, bp3);
            FFMA2(acc[1][0], ap1, bp0); FFMA2(acc[1][1], ap1, bp1);
            FFMA2(acc[1][2], ap1, bp2); FFMA2(acc[1][3], ap1, bp3);
            FFMA2(acc[2][0], ap2, bp0); FFMA2(acc[2][1], ap2, bp1);
            FFMA2(acc[2][2], ap2, bp2); FFMA2(acc[2][3], ap2, bp3);
            FFMA2(acc[3][0], ap3, bp0); FFMA2(acc[3][1], ap3, bp1);
            FFMA2(acc[3][2], ap3, bp2); FFMA2(acc[3][3], ap3, bp3);
            FFMA2(acc[4][0], ap4, bp0); FFMA2(acc[4][1], ap4, bp1);
            FFMA2(acc[4][2], ap4, bp2); FFMA2(acc[4][3], ap4, bp3);
            FFMA2(acc[5][0], ap5, bp0); FFMA2(acc[5][1], ap5, bp1);
            FFMA2(acc[5][2], ap5, bp2); FFMA2(acc[5][3], ap5, bp3);
            FFMA2(acc[6][0], ap6, bp0); FFMA2(acc[6][1], ap6, bp1);
            FFMA2(acc[6][2], ap6, bp2); FFMA2(acc[6][3], ap6, bp3);
            FFMA2(acc[7][0], ap7, bp0); FFMA2(acc[7][1], ap7, bp1);
            FFMA2(acc[7][2], ap7, bp2); FFMA2(acc[7][3], ap7, bp3);
        }

        // store prefetched tile into the other buffer (stride 256 floats)
        if (more) {
            const int nb = buf ^ 1;
            float* aS = &As2[nb][lk][2 * lrow];
            *reinterpret_cast<float2*>(aS + 0*256) = make_float2(pa0.x, pa0.x);
            *reinterpret_cast<float2*>(aS + 1*256) = make_float2(pa0.y, pa0.y);
            *reinterpret_cast<float2*>(aS + 2*256) = make_float2(pa0.z, pa0.z);
            *reinterpret_cast<float2*>(aS + 3*256) = make_float2(pa0.w, pa0.w);
            *reinterpret_cast<float2*>(aS + 4*256) = make_float2(pa1.x, pa1.x);
            *reinterpret_cast<float2*>(aS + 5*256) = make_float2(pa1.y, pa1.y);
            *reinterpret_cast<float2*>(aS + 6*256) = make_float2(pa1.z, pa1.z);
            *reinterpret_cast<float2*>(aS + 7*256) = make_float2(pa1.w, pa1.w);
            Bs[nb][lk+0][lrow]=pb0.x; Bs[nb][lk+1][lrow]=pb0.y; Bs[nb][lk+2][lrow]=pb0.z; Bs[nb][lk+3][lrow]=pb0.w;
            Bs[nb][lk+4][lrow]=pb1.x; Bs[nb][lk+5][lrow]=pb1.y; Bs[nb][lk+6][lrow]=pb1.z; Bs[nb][lk+7][lrow]=pb1.w;
        }
        __syncthreads();
    }

    #pragma unroll
    for (int i = 0; i < 8; i++) {
        int m = bm + ((i < 4) ? (mA + i) : (64 + mA + i - 4));
        #pragma unroll
        for (int qj = 0; qj < 2; qj++) {
            int n = bn + qj * 64 + nA;
            F2U p0, p1;
            p0.u = acc[i][qj*2];
            p1.u = acc[i][qj*2 + 1];
            float4 o;
            o.x = p0.f.x + bias[n];
            o.y = p0.f.y + bias[n+1];
            o.z = p1.f.x + bias[n+2];
            o.w = p1.f.y + bias[n+3];
            if (ACT == 1) {
                o.x = gelu_f(o.x); o.y = gelu_f(o.y);
                o.z = gelu_f(o.z); o.w = gelu_f(o.w);
            }
            if (MODE == 2) {
                if (!g_use[m])
                    o = *reinterpret_cast<const float4*>(&g_red[(size_t)m * 256 + n]);
            }
            *reinterpret_cast<float4*>(&C[(size_t)m * N + n]) = o;
        }
    }
}

// ---------------- LayerNorm over 256, one block per row ----------------
__global__ void ln_k(const float* __restrict__ gam, const float* __restrict__ bet)
{
    int r = blockIdx.x, tid = threadIdx.x;
    float x = g_h2[(size_t)r * 256 + tid];
    __shared__ float sh[256];
    sh[tid] = x; __syncthreads();
    for (int s = 128; s > 0; s >>= 1) { if (tid < s) sh[tid] += sh[tid + s]; __syncthreads(); }
    float mu = sh[0] * (1.0f / 256.0f);
    __syncthreads();
    float d = x - mu;
    sh[tid] = d * d; __syncthreads();
    for (int s = 128; s > 0; s >>= 1) { if (tid < s) sh[tid] += sh[tid + s]; __syncthreads(); }
    float var = sh[0] * (1.0f / 256.0f);
    g_red[(size_t)r * 256 + tid] = d * rsqrtf(var + 1e-5f) * gam[tid] + bet[tid];
}

// ---------------- attention: one block per batch, warp per head ----------------
__global__ void attn_k(const int* __restrict__ mask)
{
    int b = blockIdx.x, tid = threadIdx.x;
    int h = tid >> 5, lane = tid & 31;
    __shared__ float qs[Hsz][Ssz][33], ks[Hsz][Ssz][33], vs[Hsz][Ssz][33];
    __shared__ float sc[Hsz][Ssz][Ssz + 1];
    __shared__ int exS[Ssz];
    __shared__ int anyS;

    if (b == 0 && tid == 0) g_acc = 0.0f;
    if (tid < Ssz) exS[tid] = (mask[b * Ssz + tid] > 0);
    __syncthreads();
    if (tid == 0) { int a = 0; for (int s = 0; s < Ssz; s++) a |= exS[s]; anyS = a; }
    __syncthreads();
    if (tid < Ssz) g_use[b * Ssz + tid] = (unsigned char)((!exS[tid]) && anyS);

    #pragma unroll
    for (int s = 0; s < Ssz; s++) {
        size_t base = ((size_t)(b * Ssz + s)) * REDsz + h * DHsz + lane;
        qs[h][s][lane] = g_q[base];
        ks[h][s][lane] = g_k[base];
        vs[h][s][lane] = g_v[base];
    }
    __syncwarp();

    for (int idx = lane; idx < Ssz * Ssz; idx += 32) {
        int i = idx / Ssz, j = idx - i * Ssz;
        float dot = 0.0f;
        #pragma unroll
        for (int d = 0; d < 32; d++) dot += qs[h][i][d] * ks[h][j][d];
        sc[h][i][j] = exS[j] ? dot * 0.17677669529663687f : -1e9f;
    }
    __syncwarp();

    if (lane < Ssz) {
        int i = lane;
        float m = -1e30f;
        #pragma unroll
        for (int j = 0; j < Ssz; j++) m = fmaxf(m, sc[h][i][j]);
        float sum = 0.0f;
        #pragma unroll
        for (int j = 0; j < Ssz; j++) { float e = expf(sc[h][i][j] - m); sc[h][i][j] = e; sum += e; }
        float inv = 1.0f / sum;
        #pragma unroll
        for (int j = 0; j < Ssz; j++) sc[h][i][j] *= inv;
    }
    __syncwarp();

    #pragma unroll
    for (int i = 0; i < Ssz; i++) {
        float s = 0.0f;
        #pragma unroll
        for (int j = 0; j < Ssz; j++) s += sc[h][i][j] * vs[h][j][lane];
        g_ctx[((size_t)(b * Ssz + i)) * REDsz + h * DHsz + lane] = s;
    }
}

// ---------------- orthogonality loss: one block per batch ----------------
__global__ void loss_k()
{
    int b = blockIdx.x, tid = threadIdx.x;
    __shared__ float X[Ssz][REDsz + 1];
    __shared__ float inv[Ssz];
    for (int idx = tid; idx < Ssz * REDsz; idx += 256)
        X[idx >> 8][idx & 255] = g_upd[(size_t)b * Ssz * REDsz + idx];
    __syncthreads();
    int w = tid >> 5, lane = tid & 31;
    for (int r = w; r < Ssz; r += 8) {
        float s = 0.0f;
        for (int d = lane; d < 256; d += 32) s += X[r][d] * X[r][d];
        for (int o = 16; o > 0; o >>= 1) s += __shfl_down_sync(0xffffffffu, s, o);
        if (lane == 0) inv[r] = 1.0f / fmaxf(sqrtf(s), 1e-8f);
    }
    __syncthreads();
    float part = 0.0f;
    if (tid < (Ssz * (Ssz - 1)) / 2) {
        int p = tid, i = 0;
        while (p >= Ssz - 1 - i) { p -= Ssz - 1 - i; i++; }
        int j = i + 1 + p;
        float dot = 0.0f;
        for (int d = 0; d < 256; d++) dot += X[i][d] * X[j][d];
        float gv = fabsf(dot * inv[i] * inv[j]);
        part = fmaxf(gv - 0.1f, 0.0f) * 2.0f;
    }
    __shared__ float red[256];
    red[tid] = part; __syncthreads();
    for (int s = 128; s > 0; s >>= 1) { if (tid < s) red[tid] += red[tid + s]; __syncthreads(); }
    if (tid == 0) atomicAdd(&g_acc, red[0]);
}

// ---------------- logits: mean over S then Wp ----------------
__global__ void logit_k(const float* __restrict__ Wp, const float* __restrict__ bp,
                        float* __restrict__ out, int loff)
{
    int b = blockIdx.x, tid = threadIdx.x;
    __shared__ float mean[REDsz];
    float s = 0.0f;
    for (int ss = 0; ss < Ssz; ss++)
        s += g_upd[((size_t)(b * Ssz + ss)) * REDsz + tid];
    mean[tid] = s * (1.0f / (float)Ssz);
    __syncthreads();
    if (tid < NLAB) {
        float a = bp[tid];
        const float* wr = Wp + tid * REDsz;
        for (int d = 0; d < REDsz; d++) a += mean[d] * wr[d];
        out[loff + b * NLAB + tid] = a;
    }
}

__global__ void fin_k(float* out, int writeloss)
{
    if (writeloss)
        out[0] = g_acc * (1.0f / ((float)Bsz * Ssz * (Ssz - 1)));
}

// ---------------- launch ----------------
extern "C" void kernel_launch(void* const* d_in, const int* in_sizes, int n_in,
                              void* d_out, int out_size)
{
    const float* cls  = (const float*)d_in[0];
    const int*   mask = (const int*)  d_in[1];
    const float* miss = (const float*)d_in[2];
    const float* W1 = (const float*)d_in[3];  const float* b1 = (const float*)d_in[4];
    const float* W2 = (const float*)d_in[5];  const float* b2 = (const float*)d_in[6];
    const float* lg = (const float*)d_in[7];  const float* lb = (const float*)d_in[8];
    const float* Wq = (const float*)d_in[9];  const float* bq = (const float*)d_in[10];
    const float* Wk = (const float*)d_in[11]; const float* bk = (const float*)d_in[12];
    const float* Wv = (const float*)d_in[13]; const float* bv = (const float*)d_in[14];
    const float* Wo = (const float*)d_in[15]; const float* bo = (const float*)d_in[16];
    const float* Wp = (const float*)d_in[17]; const float* bp = (const float*)d_in[18];
    float* out = (float*)d_out;

    int loff = out_size - Bsz * NLAB;
    if (loff < 0) loff = 0;

    float *h1, *h2, *red, *q, *k, *v, *ctx, *upd;
    cudaGetSymbolAddress((void**)&h1,  g_h1);
    cudaGetSymbolAddress((void**)&h2,  g_h2);
    cudaGetSymbolAddress((void**)&red, g_red);
    cudaGetSymbolAddress((void**)&q,   g_q);
    cudaGetSymbolAddress((void**)&k,   g_k);
    cudaGetSymbolAddress((void**)&v,   g_v);
    cudaGetSymbolAddress((void**)&ctx, g_ctx);
    cudaGetSymbolAddress((void**)&upd, g_upd);

    dim3 blk(256);
    // 1) gather + GEMM1 + GELU : [M,768] -> [M,384]
    gemm128_k<1,1><<<dim3(384/128, Mrows/128), blk>>>(
        nullptr, W1, nullptr, nullptr, b1, nullptr, nullptr,
        h1, nullptr, nullptr, 384, 768, cls, miss, mask);
    // 2) GEMM2 + GELU : [M,384] -> [M,256]
    gemm128_k<1,0><<<dim3(256/128, Mrows/128), blk>>>(
        h1, W2, nullptr, nullptr, b2, nullptr, nullptr,
        h2, nullptr, nullptr, 256, 384, nullptr, nullptr, nullptr);
    // 3) LayerNorm -> g_red
    ln_k<<<Mrows, blk>>>(lg, lb);
    // 4) fused QKV projections
    gemm128_k<0,3><<<dim3(6, Mrows/128), blk>>>(
        red, Wq, Wk, Wv, bq, bk, bv,
        q, k, v, 256, 256, nullptr, nullptr, nullptr);
    // 5) attention (also computes g_use, zeroes g_acc)
    attn_k<<<Bsz, blk>>>(mask);
    // 6) Wo projection + scatter-select epilogue -> g_upd
    gemm128_k<0,2><<<dim3(256/128, Mrows/128), blk>>>(
        ctx, Wo, nullptr, nullptr, bo, nullptr, nullptr,
        upd, nullptr, nullptr, 256, 256, nullptr, nullptr, nullptr);
    // 7) orthogonality loss accumulate
    loss_k<<<Bsz, blk>>>();
    // 8) logits
    logit_k<<<Bsz, blk>>>(Wp, bp, out, loff);
    // 9) finalize loss scalar
    fin_k<<<1, 1>>>(out, loff >= 1 ? 1 : 0);
}

// round 8
// speedup vs baseline: 1.9708x; 1.9708x over previous
#include <cuda_runtime.h>
#include <math.h>
#include <stdint.h>

#define Bsz   2048
#define Ssz   23
#define Esz   768
#define REDsz 256
#define Hsz   8
#define DHsz  32
#define NLAB  25
#define Mrows (Bsz*Ssz)   // 47104 = 368*128

// ---------------- scratch (allocation-free) ----------------
__device__ float g_h1 [(size_t)Mrows*384];
__device__ float g_h2 [(size_t)Mrows*256];
__device__ float g_red[(size_t)Mrows*256];
__device__ float g_q  [(size_t)Mrows*256];
__device__ float g_k  [(size_t)Mrows*256];
__device__ float g_v  [(size_t)Mrows*256];
__device__ float g_ctx[(size_t)Mrows*256];
__device__ float g_upd[(size_t)Mrows*256];
__device__ unsigned char g_use[Mrows];
__device__ float g_acc;

__device__ __forceinline__ float gelu_f(float x) {
    return 0.5f * x * (1.0f + erff(x * 0.70710678118654752440f));
}

__device__ __forceinline__ float tf32_rna(float x) {
    uint32_t r;
    asm("cvt.rna.tf32.f32 %0, %1;" : "=r"(r) : "f"(x));
    return __uint_as_float(r);
}

// mma.sync m16n8k8 tf32 (sm_80+ baseline; legal on compute_103)
__device__ __forceinline__ void mma_tf32(float* d, const uint32_t* a, const uint32_t* b) {
    asm volatile(
        "mma.sync.aligned.m16n8k8.row.col.f32.tf32.tf32.f32 "
        "{%0,%1,%2,%3}, {%4,%5,%6,%7}, {%8,%9}, {%0,%1,%2,%3};"
        : "+f"(d[0]), "+f"(d[1]), "+f"(d[2]), "+f"(d[3])
        : "r"(a[0]), "r"(a[1]), "r"(a[2]), "r"(a[3]), "r"(b[0]), "r"(b[1]));
}

// ---------------- HMMA tf32 GEMM: C = act(A @ W^T + bias) ----------------
// BM=BN=128, BK=32, 256 threads (8 warps), warp tile 64x32 (4 m16 x 4 n8).
// MODE 0: plain. MODE 1: A gathered from cls/missing by mask (K=Esz).
// MODE 2: epilogue select vs g_red (N=256). MODE 3: fused QKV (grid.x=6).
template<int ACT, int MODE>
__global__ void __launch_bounds__(256, 2) mmagemm_k(
    const float* __restrict__ A,
    const float* __restrict__ Wa, const float* __restrict__ Wb, const float* __restrict__ Wc,
    const float* __restrict__ ba, const float* __restrict__ bb, const float* __restrict__ bc,
    float* __restrict__ Ca, float* __restrict__ Cb, float* __restrict__ Cc,
    int N, int K,
    const float* __restrict__ cls, const float* __restrict__ miss,
    const int* __restrict__ mask)
{
    __shared__ float sA[128][36];   // pad 36: fragment LDS conflict-free
    __shared__ float sB[128][36];

    const int tid  = threadIdx.x;
    const int lane = tid & 31;
    const int wid  = tid >> 5;
    const int g    = lane >> 2;     // 0..7
    const int tg   = lane & 3;      // 0..3
    const int wm   = wid & 1;       // m-half (64 rows)
    const int wn   = wid >> 1;      // n-quarter (32 cols)
    const int bm   = blockIdx.y * 128;

    const float* W; const float* bias; float* C; int bn;
    if (MODE == 3) {
        int sel = blockIdx.x >> 1;
        W    = sel == 0 ? Wa : sel == 1 ? Wb : Wc;
        bias = sel == 0 ? ba : sel == 1 ? bb : bc;
        C    = sel == 0 ? Ca : sel == 1 ? Cb : Cc;
        bn = (blockIdx.x & 1) * 128;
    } else {
        W = Wa; bias = ba; C = Ca;
        bn = blockIdx.x * 128;
    }

    // staging map: each thread loads one row-half (16 floats) of A and B per k-tile
    const int srow = tid >> 1;            // 0..127
    const int colb = (tid & 1) * 16;      // 0 or 16

    const float* Arow;
    if (MODE == 1) {
        int r = bm + srow;
        Arow = (mask[r] > 0) ? (cls + (size_t)r * Esz)
                             : (miss + (size_t)(r % Ssz) * Esz);
    } else {
        Arow = A + (size_t)(bm + srow) * K;
    }
    const float* Brow = W + (size_t)(bn + srow) * K;

    float acc[4][4][4] = {};   // [mt][nt][reg]
    float4 pa[2], pb[2];       // prefetch regs (half k-tile granularity x2)
    float4 qa[2], qb[2];

    // prefetch k-tile 0
    pa[0] = *reinterpret_cast<const float4*>(Arow + colb + 0);
    pa[1] = *reinterpret_cast<const float4*>(Arow + colb + 4);
    qa[0] = *reinterpret_cast<const float4*>(Arow + colb + 8);
    qa[1] = *reinterpret_cast<const float4*>(Arow + colb + 12);
    pb[0] = *reinterpret_cast<const float4*>(Brow + colb + 0);
    pb[1] = *reinterpret_cast<const float4*>(Brow + colb + 4);
    qb[0] = *reinterpret_cast<const float4*>(Brow + colb + 8);
    qb[1] = *reinterpret_cast<const float4*>(Brow + colb + 12);

    const int nT = K >> 5;
    for (int t = 0; t < nT; t++) {
        // cvt + STS current tile
        {
            float4 v;
            #pragma unroll
            for (int q = 0; q < 2; q++) {
                v = pa[q];
                v.x = tf32_rna(v.x); v.y = tf32_rna(v.y); v.z = tf32_rna(v.z); v.w = tf32_rna(v.w);
                *reinterpret_cast<float4*>(&sA[srow][colb + q*4]) = v;
                v = qa[q];
                v.x = tf32_rna(v.x); v.y = tf32_rna(v.y); v.z = tf32_rna(v.z); v.w = tf32_rna(v.w);
                *reinterpret_cast<float4*>(&sA[srow][colb + 8 + q*4]) = v;
                v = pb[q];
                v.x = tf32_rna(v.x); v.y = tf32_rna(v.y); v.z = tf32_rna(v.z); v.w = tf32_rna(v.w);
                *reinterpret_cast<float4*>(&sB[srow][colb + q*4]) = v;
                v = qb[q];
                v.x = tf32_rna(v.x); v.y = tf32_rna(v.y); v.z = tf32_rna(v.z); v.w = tf32_rna(v.w);
                *reinterpret_cast<float4*>(&sB[srow][colb + 8 + q*4]) = v;
            }
        }
        __syncthreads();

        // prefetch next tile
        if (t + 1 < nT) {
            int k0 = (t + 1) << 5;
            pa[0] = *reinterpret_cast<const float4*>(Arow + k0 + colb + 0);
            pa[1] = *reinterpret_cast<const float4*>(Arow + k0 + colb + 4);
            qa[0] = *reinterpret_cast<const float4*>(Arow + k0 + colb + 8);
            qa[1] = *reinterpret_cast<const float4*>(Arow + k0 + colb + 12);
            pb[0] = *reinterpret_cast<const float4*>(Brow + k0 + colb + 0);
            pb[1] = *reinterpret_cast<const float4*>(Brow + k0 + colb + 4);
            qb[0] = *reinterpret_cast<const float4*>(Brow + k0 + colb + 8);
            qb[1] = *reinterpret_cast<const float4*>(Brow + k0 + colb + 12);
        }

        // MMA: 4 k-steps of 8
        #pragma unroll
        for (int ks = 0; ks < 4; ks++) {
            const int kk = ks << 3;
            uint32_t af[4][4];
            #pragma unroll
            for (int mt = 0; mt < 4; mt++) {
                int r0 = wm * 64 + mt * 16 + g;
                af[mt][0] = __float_as_uint(sA[r0    ][kk + tg]);
                af[mt][1] = __float_as_uint(sA[r0 + 8][kk + tg]);
                af[mt][2] = __float_as_uint(sA[r0    ][kk + tg + 4]);
                af[mt][3] = __float_as_uint(sA[r0 + 8][kk + tg + 4]);
            }
            uint32_t bf[4][2];
            #pragma unroll
            for (int nt = 0; nt < 4; nt++) {
                int n0 = wn * 32 + nt * 8 + g;
                bf[nt][0] = __float_as_uint(sB[n0][kk + tg]);
                bf[nt][1] = __float_as_uint(sB[n0][kk + tg + 4]);
            }
            #pragma unroll
            for (int mt = 0; mt < 4; mt++)
                #pragma unroll
                for (int nt = 0; nt < 4; nt++)
                    mma_tf32(acc[mt][nt], af[mt], bf[nt]);
        }
        __syncthreads();
    }

    // epilogue: d0=(g,2tg) d1=(g,2tg+1) d2=(g+8,2tg) d3=(g+8,2tg+1)
    #pragma unroll
    for (int mt = 0; mt < 4; mt++) {
        int m0 = bm + wm * 64 + mt * 16 + g;
        int m1 = m0 + 8;
        bool k0 = true, k1 = true;
        if (MODE == 2) { k0 = g_use[m0] != 0; k1 = g_use[m1] != 0; }
        #pragma unroll
        for (int nt = 0; nt < 4; nt++) {
            int n = bn + wn * 32 + nt * 8 + 2 * tg;
            float2 bz = *reinterpret_cast<const float2*>(bias + n);
            float2 o0, o1;
            o0.x = acc[mt][nt][0] + bz.x; o0.y = acc[mt][nt][1] + bz.y;
            o1.x = acc[mt][nt][2] + bz.x; o1.y = acc[mt][nt][3] + bz.y;
            if (ACT == 1) {
                o0.x = gelu_f(o0.x); o0.y = gelu_f(o0.y);
                o1.x = gelu_f(o1.x); o1.y = gelu_f(o1.y);
            }
            if (MODE == 2) {
                if (!k0) o0 = *reinterpret_cast<const float2*>(&g_red[(size_t)m0 * 256 + n]);
                if (!k1) o1 = *reinterpret_cast<const float2*>(&g_red[(size_t)m1 * 256 + n]);
            }
            *reinterpret_cast<float2*>(&C[(size_t)m0 * N + n]) = o0;
            *reinterpret_cast<float2*>(&C[(size_t)m1 * N + n]) = o1;
        }
    }
}

// ---------------- LayerNorm over 256, one block per row ----------------
__global__ void ln_k(const float* __restrict__ gam, const float* __restrict__ bet)
{
    int r = blockIdx.x, tid = threadIdx.x;
    float x = g_h2[(size_t)r * 256 + tid];
    __shared__ float sh[256];
    sh[tid] = x; __syncthreads();
    for (int s = 128; s > 0; s >>= 1) { if (tid < s) sh[tid] += sh[tid + s]; __syncthreads(); }
    float mu = sh[0] * (1.0f / 256.0f);
    __syncthreads();
    float d = x - mu;
    sh[tid] = d * d; __syncthreads();
    for (int s = 128; s > 0; s >>= 1) { if (tid < s) sh[tid] += sh[tid + s]; __syncthreads(); }
    float var = sh[0] * (1.0f / 256.0f);
    g_red[(size_t)r * 256 + tid] = d * rsqrtf(var + 1e-5f) * gam[tid] + bet[tid];
}

// ---------------- attention: one block per batch, warp per head ----------------
__global__ void attn_k(const int* __restrict__ mask)
{
    int b = blockIdx.x, tid = threadIdx.x;
    int h = tid >> 5, lane = tid & 31;
    __shared__ float qs[Hsz][Ssz][33], ks[Hsz][Ssz][33], vs[Hsz][Ssz][33];
    __shared__ float sc[Hsz][Ssz][Ssz + 1];
    __shared__ int exS[Ssz];
    __shared__ int anyS;

    if (b == 0 && tid == 0) g_acc = 0.0f;
    if (tid < Ssz) exS[tid] = (mask[b * Ssz + tid] > 0);
    __syncthreads();
    if (tid == 0) { int a = 0; for (int s = 0; s < Ssz; s++) a |= exS[s]; anyS = a; }
    __syncthreads();
    if (tid < Ssz) g_use[b * Ssz + tid] = (unsigned char)((!exS[tid]) && anyS);

    #pragma unroll
    for (int s = 0; s < Ssz; s++) {
        size_t base = ((size_t)(b * Ssz + s)) * REDsz + h * DHsz + lane;
        qs[h][s][lane] = g_q[base];
        ks[h][s][lane] = g_k[base];
        vs[h][s][lane] = g_v[base];
    }
    __syncwarp();

    for (int idx = lane; idx < Ssz * Ssz; idx += 32) {
        int i = idx / Ssz, j = idx - i * Ssz;
        float dot = 0.0f;
        #pragma unroll
        for (int d = 0; d < 32; d++) dot += qs[h][i][d] * ks[h][j][d];
        sc[h][i][j] = exS[j] ? dot * 0.17677669529663687f : -1e9f;
    }
    __syncwarp();

    if (lane < Ssz) {
        int i = lane;
        float m = -1e30f;
        #pragma unroll
        for (int j = 0; j < Ssz; j++) m = fmaxf(m, sc[h][i][j]);
        float sum = 0.0f;
        #pragma unroll
        for (int j = 0; j < Ssz; j++) { float e = expf(sc[h][i][j] - m); sc[h][i][j] = e; sum += e; }
        float inv = 1.0f / sum;
        #pragma unroll
        for (int j = 0; j < Ssz; j++) sc[h][i][j] *= inv;
    }
    __syncwarp();

    #pragma unroll
    for (int i = 0; i < Ssz; i++) {
        float s = 0.0f;
        #pragma unroll
        for (int j = 0; j < Ssz; j++) s += sc[h][i][j] * vs[h][j][lane];
        g_ctx[((size_t)(b * Ssz + i)) * REDsz + h * DHsz + lane] = s;
    }
}

// ---------------- orthogonality loss: one block per batch ----------------
__global__ void loss_k()
{
    int b = blockIdx.x, tid = threadIdx.x;
    __shared__ float X[Ssz][REDsz + 1];
    __shared__ float inv[Ssz];
    for (int idx = tid; idx < Ssz * REDsz; idx += 256)
        X[idx >> 8][idx & 255] = g_upd[(size_t)b * Ssz * REDsz + idx];
    __syncthreads();
    int w = tid >> 5, lane = tid & 31;
    for (int r = w; r < Ssz; r += 8) {
        float s = 0.0f;
        for (int d = lane; d < 256; d += 32) s += X[r][d] * X[r][d];
        for (int o = 16; o > 0; o >>= 1) s += __shfl_down_sync(0xffffffffu, s, o);
        if (lane == 0) inv[r] = 1.0f / fmaxf(sqrtf(s), 1e-8f);
    }
    __syncthreads();
    float part = 0.0f;
    if (tid < (Ssz * (Ssz - 1)) / 2) {
        int p = tid, i = 0;
        while (p >= Ssz - 1 - i) { p -= Ssz - 1 - i; i++; }
        int j = i + 1 + p;
        float dot = 0.0f;
        for (int d = 0; d < 256; d++) dot += X[i][d] * X[j][d];
        float gv = fabsf(dot * inv[i] * inv[j]);
        part = fmaxf(gv - 0.1f, 0.0f) * 2.0f;
    }
    __shared__ float red[256];
    red[tid] = part; __syncthreads();
    for (int s = 128; s > 0; s >>= 1) { if (tid < s) red[tid] += red[tid + s]; __syncthreads(); }
    if (tid == 0) atomicAdd(&g_acc, red[0]);
}

// ---------------- logits: mean over S then Wp ----------------
__global__ void logit_k(const float* __restrict__ Wp, const float* __restrict__ bp,
                        float* __restrict__ out, int loff)
{
    int b = blockIdx.x, tid = threadIdx.x;
    __shared__ float mean[REDsz];
    float s = 0.0f;
    for (int ss = 0; ss < Ssz; ss++)
        s += g_upd[((size_t)(b * Ssz + ss)) * REDsz + tid];
    mean[tid] = s * (1.0f / (float)Ssz);
    __syncthreads();
    if (tid < NLAB) {
        float a = bp[tid];
        const float* wr = Wp + tid * REDsz;
        for (int d = 0; d < REDsz; d++) a += mean[d] * wr[d];
        out[loff + b * NLAB + tid] = a;
    }
}

__global__ void fin_k(float* out, int writeloss)
{
    if (writeloss)
        out[0] = g_acc * (1.0f / ((float)Bsz * Ssz * (Ssz - 1)));
}

// ---------------- launch ----------------
extern "C" void kernel_launch(void* const* d_in, const int* in_sizes, int n_in,
                              void* d_out, int out_size)
{
    const float* cls  = (const float*)d_in[0];
    const int*   mask = (const int*)  d_in[1];
    const float* miss = (const float*)d_in[2];
    const float* W1 = (const float*)d_in[3];  const float* b1 = (const float*)d_in[4];
    const float* W2 = (const float*)d_in[5];  const float* b2 = (const float*)d_in[6];
    const float* lg = (const float*)d_in[7];  const float* lb = (const float*)d_in[8];
    const float* Wq = (const float*)d_in[9];  const float* bq = (const float*)d_in[10];
    const float* Wk = (const float*)d_in[11]; const float* bk = (const float*)d_in[12];
    const float* Wv = (const float*)d_in[13]; const float* bv = (const float*)d_in[14];
    const float* Wo = (const float*)d_in[15]; const float* bo = (const float*)d_in[16];
    const float* Wp = (const float*)d_in[17]; const float* bp = (const float*)d_in[18];
    float* out = (float*)d_out;

    int loff = out_size - Bsz * NLAB;
    if (loff < 0) loff = 0;

    float *h1, *h2, *red, *q, *k, *v, *ctx, *upd;
    cudaGetSymbolAddress((void**)&h1,  g_h1);
    cudaGetSymbolAddress((void**)&h2,  g_h2);
    cudaGetSymbolAddress((void**)&red, g_red);
    cudaGetSymbolAddress((void**)&q,   g_q);
    cudaGetSymbolAddress((void**)&k,   g_k);
    cudaGetSymbolAddress((void**)&v,   g_v);
    cudaGetSymbolAddress((void**)&ctx, g_ctx);
    cudaGetSymbolAddress((void**)&upd, g_upd);

    dim3 blk(256);
    // 1) gather + GEMM1 + GELU : [M,768] -> [M,384]
    mmagemm_k<1,1><<<dim3(3, Mrows/128), blk>>>(
        nullptr, W1, nullptr, nullptr, b1, nullptr, nullptr,
        h1, nullptr, nullptr, 384, 768, cls, miss, mask);
    // 2) GEMM2 + GELU : [M,384] -> [M,256]
    mmagemm_k<1,0><<<dim3(2, Mrows/128), blk>>>(
        h1, W2, nullptr, nullptr, b2, nullptr, nullptr,
        h2, nullptr, nullptr, 256, 384, nullptr, nullptr, nullptr);
    // 3) LayerNorm -> g_red
    ln_k<<<Mrows, 256>>>(lg, lb);
    // 4) fused QKV projections
    mmagemm_k<0,3><<<dim3(6, Mrows/128), blk>>>(
        red, Wq, Wk, Wv, bq, bk, bv,
        q, k, v, 256, 256, nullptr, nullptr, nullptr);
    // 5) attention (also computes g_use, zeroes g_acc)
    attn_k<<<Bsz, 256>>>(mask);
    // 6) Wo projection + scatter-select epilogue -> g_upd
    mmagemm_k<0,2><<<dim3(2, Mrows/128), blk>>>(
        ctx, Wo, nullptr, nullptr, bo, nullptr, nullptr,
        upd, nullptr, nullptr, 256, 256, nullptr, nullptr, nullptr);
    // 7) orthogonality loss accumulate
    loss_k<<<Bsz, 256>>>();
    // 8) logits
    logit_k<<<Bsz, 256>>>(Wp, bp, out, loff);
    // 9) finalize loss scalar
    fin_k<<<1, 1>>>(out, loff >= 1 ? 1 : 0);
}

// round 9
// speedup vs baseline: 2.2259x; 1.1294x over previous
#include <cuda_runtime.h>
#include <math.h>
#include <stdint.h>

#define Bsz   2048
#define Ssz   23
#define Esz   768
#define REDsz 256
#define Hsz   8
#define DHsz  32
#define NLAB  25
#define Mrows (Bsz*Ssz)   // 47104 = 368*128

// ---------------- scratch (allocation-free) ----------------
__device__ float g_h1 [(size_t)Mrows*384];
__device__ float g_h2 [(size_t)Mrows*256];
__device__ float g_red[(size_t)Mrows*256];
__device__ float g_q  [(size_t)Mrows*256];
__device__ float g_k  [(size_t)Mrows*256];
__device__ float g_v  [(size_t)Mrows*256];
__device__ float g_ctx[(size_t)Mrows*256];
__device__ float g_upd[(size_t)Mrows*256];
__device__ unsigned char g_use[Mrows];
__device__ float g_acc;

__device__ __forceinline__ float gelu_f(float x) {
    return 0.5f * x * (1.0f + erff(x * 0.70710678118654752440f));
}

__device__ __forceinline__ float tf32_rna(float x) {
    uint32_t r;
    asm("cvt.rna.tf32.f32 %0, %1;" : "=r"(r) : "f"(x));
    return __uint_as_float(r);
}

__device__ __forceinline__ uint32_t smem_u32(const void* p) {
    uint32_t a;
    asm("{ .reg .u64 t; cvta.to.shared.u64 t, %1; cvt.u32.u64 %0, t; }" : "=r"(a) : "l"(p));
    return a;
}

// mma.sync m16n8k8 tf32 (sm_80+ baseline; legal on compute_103)
__device__ __forceinline__ void mma_tf32(float* d, const uint32_t* a, const uint32_t* b) {
    asm volatile(
        "mma.sync.aligned.m16n8k8.row.col.f32.tf32.tf32.f32 "
        "{%0,%1,%2,%3}, {%4,%5,%6,%7}, {%8,%9}, {%0,%1,%2,%3};"
        : "+f"(d[0]), "+f"(d[1]), "+f"(d[2]), "+f"(d[3])
        : "r"(a[0]), "r"(a[1]), "r"(a[2]), "r"(a[3]), "r"(b[0]), "r"(b[1]));
}

#define LDSM_X4(r0_, r1_, r2_, r3_, addr_) \
    asm volatile("ldmatrix.sync.aligned.m8n8.x4.shared.b16 {%0,%1,%2,%3}, [%4];" \
                 : "=r"(r0_), "=r"(r1_), "=r"(r2_), "=r"(r3_) : "r"(addr_))
#define LDSM_X2(r0_, r1_, addr_) \
    asm volatile("ldmatrix.sync.aligned.m8n8.x2.shared.b16 {%0,%1}, [%2];" \
                 : "=r"(r0_), "=r"(r1_) : "r"(addr_))

// ---------------- HMMA tf32 GEMM: C = act(A @ W^T + bias) ----------------
// BM=BN=128, BK=32, 256 threads (8 warps), warp tile 64x32 (4 m16 x 4 n8).
// Fragments loaded via ldmatrix (conflict-free with 36-float row pad).
// MODE 0: plain. MODE 1: A gathered from cls/missing by mask (K=Esz).
// MODE 2: epilogue select vs g_red (N=256). MODE 3: fused QKV (grid.x=6).
template<int ACT, int MODE>
__global__ void __launch_bounds__(256, 2) mmagemm_k(
    const float* __restrict__ A,
    const float* __restrict__ Wa, const float* __restrict__ Wb, const float* __restrict__ Wc,
    const float* __restrict__ ba, const float* __restrict__ bb, const float* __restrict__ bc,
    float* __restrict__ Ca, float* __restrict__ Cb, float* __restrict__ Cc,
    int N, int K,
    const float* __restrict__ cls, const float* __restrict__ miss,
    const int* __restrict__ mask)
{
    __shared__ float sA[128][36];   // pad 36: ldmatrix conflict-free
    __shared__ float sB[128][36];

    const int tid  = threadIdx.x;
    const int lane = tid & 31;
    const int wid  = tid >> 5;
    const int g    = lane >> 2;     // 0..7
    const int tg   = lane & 3;      // 0..3
    const int wm   = wid & 1;       // m-half (64 rows)
    const int wn   = wid >> 1;      // n-quarter (32 cols)
    const int bm   = blockIdx.y * 128;

    const float* W; const float* bias; float* C; int bn;
    if (MODE == 3) {
        int sel = blockIdx.x >> 1;
        W    = sel == 0 ? Wa : sel == 1 ? Wb : Wc;
        bias = sel == 0 ? ba : sel == 1 ? bb : bc;
        C    = sel == 0 ? Ca : sel == 1 ? Cb : Cc;
        bn = (blockIdx.x & 1) * 128;
    } else {
        W = Wa; bias = ba; C = Ca;
        bn = blockIdx.x * 128;
    }

    // ldmatrix per-lane base addresses
    const int lr = lane & 7;        // row within 8x8 matrix
    const int li = lane >> 3;       // matrix index 0..3
    const uint32_t aBase = smem_u32(&sA[0][0]) +
        (uint32_t)(((wm * 64 + (li & 1) * 8 + lr) * 36 + (li >> 1) * 4) * 4);
    const uint32_t bBase = smem_u32(&sB[0][0]) +
        (uint32_t)(((wn * 32 + lr) * 36 + (li & 1) * 4) * 4);

    // staging map: each thread loads one row-half (16 floats) of A and B per k-tile
    const int srow = tid >> 1;            // 0..127
    const int colb = (tid & 1) * 16;      // 0 or 16

    const float* Arow;
    if (MODE == 1) {
        int r = bm + srow;
        Arow = (mask[r] > 0) ? (cls + (size_t)r * Esz)
                             : (miss + (size_t)(r % Ssz) * Esz);
    } else {
        Arow = A + (size_t)(bm + srow) * K;
    }
    const float* Brow = W + (size_t)(bn + srow) * K;

    float acc[4][4][4] = {};   // [mt][nt][reg]
    float4 pa[2], pb[2];
    float4 qa[2], qb[2];

    // prefetch k-tile 0
    pa[0] = *reinterpret_cast<const float4*>(Arow + colb + 0);
    pa[1] = *reinterpret_cast<const float4*>(Arow + colb + 4);
    qa[0] = *reinterpret_cast<const float4*>(Arow + colb + 8);
    qa[1] = *reinterpret_cast<const float4*>(Arow + colb + 12);
    pb[0] = *reinterpret_cast<const float4*>(Brow + colb + 0);
    pb[1] = *reinterpret_cast<const float4*>(Brow + colb + 4);
    qb[0] = *reinterpret_cast<const float4*>(Brow + colb + 8);
    qb[1] = *reinterpret_cast<const float4*>(Brow + colb + 12);

    const int nT = K >> 5;
    for (int t = 0; t < nT; t++) {
        // cvt + STS current tile
        {
            float4 v;
            #pragma unroll
            for (int q = 0; q < 2; q++) {
                v = pa[q];
                v.x = tf32_rna(v.x); v.y = tf32_rna(v.y); v.z = tf32_rna(v.z); v.w = tf32_rna(v.w);
                *reinterpret_cast<float4*>(&sA[srow][colb + q*4]) = v;
                v = qa[q];
                v.x = tf32_rna(v.x); v.y = tf32_rna(v.y); v.z = tf32_rna(v.z); v.w = tf32_rna(v.w);
                *reinterpret_cast<float4*>(&sA[srow][colb + 8 + q*4]) = v;
                v = pb[q];
                v.x = tf32_rna(v.x); v.y = tf32_rna(v.y); v.z = tf32_rna(v.z); v.w = tf32_rna(v.w);
                *reinterpret_cast<float4*>(&sB[srow][colb + q*4]) = v;
                v = qb[q];
                v.x = tf32_rna(v.x); v.y = tf32_rna(v.y); v.z = tf32_rna(v.z); v.w = tf32_rna(v.w);
                *reinterpret_cast<float4*>(&sB[srow][colb + 8 + q*4]) = v;
            }
        }
        __syncthreads();

        // prefetch next tile
        if (t + 1 < nT) {
            int k0 = (t + 1) << 5;
            pa[0] = *reinterpret_cast<const float4*>(Arow + k0 + colb + 0);
            pa[1] = *reinterpret_cast<const float4*>(Arow + k0 + colb + 4);
            qa[0] = *reinterpret_cast<const float4*>(Arow + k0 + colb + 8);
            qa[1] = *reinterpret_cast<const float4*>(Arow + k0 + colb + 12);
            pb[0] = *reinterpret_cast<const float4*>(Brow + k0 + colb + 0);
            pb[1] = *reinterpret_cast<const float4*>(Brow + k0 + colb + 4);
            qb[0] = *reinterpret_cast<const float4*>(Brow + k0 + colb + 8);
            qb[1] = *reinterpret_cast<const float4*>(Brow + k0 + colb + 12);
        }

        // MMA: 4 k-steps of 8, fragments via ldmatrix
        #pragma unroll
        for (int ks = 0; ks < 4; ks++) {
            const uint32_t kOff = (uint32_t)(ks * 32);   // 8 floats = 32 bytes
            uint32_t af[4][4];
            #pragma unroll
            for (int mt = 0; mt < 4; mt++)
                LDSM_X4(af[mt][0], af[mt][1], af[mt][2], af[mt][3],
                        aBase + (uint32_t)(mt * 2304) + kOff);   // 16*36*4
            uint32_t bf[4][2];
            #pragma unroll
            for (int nt = 0; nt < 4; nt++)
                LDSM_X2(bf[nt][0], bf[nt][1],
                        bBase + (uint32_t)(nt * 1152) + kOff);   // 8*36*4
            #pragma unroll
            for (int mt = 0; mt < 4; mt++)
                #pragma unroll
                for (int nt = 0; nt < 4; nt++)
                    mma_tf32(acc[mt][nt], af[mt], bf[nt]);
        }
        __syncthreads();
    }

    // epilogue: d0=(g,2tg) d1=(g,2tg+1) d2=(g+8,2tg) d3=(g+8,2tg+1)
    #pragma unroll
    for (int mt = 0; mt < 4; mt++) {
        int m0 = bm + wm * 64 + mt * 16 + g;
        int m1 = m0 + 8;
        bool k0 = true, k1 = true;
        if (MODE == 2) { k0 = g_use[m0] != 0; k1 = g_use[m1] != 0; }
        #pragma unroll
        for (int nt = 0; nt < 4; nt++) {
            int n = bn + wn * 32 + nt * 8 + 2 * tg;
            float2 bz = *reinterpret_cast<const float2*>(bias + n);
            float2 o0, o1;
            o0.x = acc[mt][nt][0] + bz.x; o0.y = acc[mt][nt][1] + bz.y;
            o1.x = acc[mt][nt][2] + bz.x; o1.y = acc[mt][nt][3] + bz.y;
            if (ACT == 1) {
                o0.x = gelu_f(o0.x); o0.y = gelu_f(o0.y);
                o1.x = gelu_f(o1.x); o1.y = gelu_f(o1.y);
            }
            if (MODE == 2) {
                if (!k0) o0 = *reinterpret_cast<const float2*>(&g_red[(size_t)m0 * 256 + n]);
                if (!k1) o1 = *reinterpret_cast<const float2*>(&g_red[(size_t)m1 * 256 + n]);
            }
            *reinterpret_cast<float2*>(&C[(size_t)m0 * N + n]) = o0;
            *reinterpret_cast<float2*>(&C[(size_t)m1 * N + n]) = o1;
        }
    }
}

// ---------------- LayerNorm over 256: one WARP per row ----------------
__global__ void ln_k(const float* __restrict__ gam, const float* __restrict__ bet)
{
    const int wid = threadIdx.x >> 5, lane = threadIdx.x & 31;
    const int r = blockIdx.x * 8 + wid;
    const float* x = &g_h2[(size_t)r * 256 + lane * 8];
    float4 v0 = *reinterpret_cast<const float4*>(x);
    float4 v1 = *reinterpret_cast<const float4*>(x + 4);
    float s = v0.x+v0.y+v0.z+v0.w + v1.x+v1.y+v1.z+v1.w;
    #pragma unroll
    for (int o = 16; o > 0; o >>= 1) s += __shfl_xor_sync(0xffffffffu, s, o);
    float mu = s * (1.0f / 256.0f);
    float d0x=v0.x-mu, d0y=v0.y-mu, d0z=v0.z-mu, d0w=v0.w-mu;
    float d1x=v1.x-mu, d1y=v1.y-mu, d1z=v1.z-mu, d1w=v1.w-mu;
    float sq = d0x*d0x+d0y*d0y+d0z*d0z+d0w*d0w + d1x*d1x+d1y*d1y+d1z*d1z+d1w*d1w;
    #pragma unroll
    for (int o = 16; o > 0; o >>= 1) sq += __shfl_xor_sync(0xffffffffu, sq, o);
    float rs = rsqrtf(sq * (1.0f / 256.0f) + 1e-5f);
    float4 ga0 = *reinterpret_cast<const float4*>(gam + lane * 8);
    float4 ga1 = *reinterpret_cast<const float4*>(gam + lane * 8 + 4);
    float4 be0 = *reinterpret_cast<const float4*>(bet + lane * 8);
    float4 be1 = *reinterpret_cast<const float4*>(bet + lane * 8 + 4);
    float4 o0, o1;
    o0.x = d0x*rs*ga0.x + be0.x; o0.y = d0y*rs*ga0.y + be0.y;
    o0.z = d0z*rs*ga0.z + be0.z; o0.w = d0w*rs*ga0.w + be0.w;
    o1.x = d1x*rs*ga1.x + be1.x; o1.y = d1y*rs*ga1.y + be1.y;
    o1.z = d1z*rs*ga1.z + be1.z; o1.w = d1w*rs*ga1.w + be1.w;
    float* y = &g_red[(size_t)r * 256 + lane * 8];
    *reinterpret_cast<float4*>(y)     = o0;
    *reinterpret_cast<float4*>(y + 4) = o1;
}

// ---------------- attention: one block per batch, warp per head ----------------
__global__ void attn_k(const int* __restrict__ mask)
{
    int b = blockIdx.x, tid = threadIdx.x;
    int h = tid >> 5, lane = tid & 31;
    __shared__ float qs[Hsz][Ssz][33], ks[Hsz][Ssz][33], vs[Hsz][Ssz][33];
    __shared__ float sc[Hsz][Ssz][Ssz + 1];
    __shared__ int exS[Ssz];
    __shared__ int anyS;

    if (b == 0 && tid == 0) g_acc = 0.0f;
    if (tid < Ssz) exS[tid] = (mask[b * Ssz + tid] > 0);
    __syncthreads();
    if (tid == 0) { int a = 0; for (int s = 0; s < Ssz; s++) a |= exS[s]; anyS = a; }
    __syncthreads();
    if (tid < Ssz) g_use[b * Ssz + tid] = (unsigned char)((!exS[tid]) && anyS);

    #pragma unroll
    for (int s = 0; s < Ssz; s++) {
        size_t base = ((size_t)(b * Ssz + s)) * REDsz + h * DHsz + lane;
        qs[h][s][lane] = g_q[base];
        ks[h][s][lane] = g_k[base];
        vs[h][s][lane] = g_v[base];
    }
    __syncwarp();

    for (int idx = lane; idx < Ssz * Ssz; idx += 32) {
        int i = idx / Ssz, j = idx - i * Ssz;
        float dot = 0.0f;
        #pragma unroll
        for (int d = 0; d < 32; d++) dot += qs[h][i][d] * ks[h][j][d];
        sc[h][i][j] = exS[j] ? dot * 0.17677669529663687f : -1e9f;
    }
    __syncwarp();

    if (lane < Ssz) {
        int i = lane;
        float m = -1e30f;
        #pragma unroll
        for (int j = 0; j < Ssz; j++) m = fmaxf(m, sc[h][i][j]);
        float sum = 0.0f;
        #pragma unroll
        for (int j = 0; j < Ssz; j++) { float e = expf(sc[h][i][j] - m); sc[h][i][j] = e; sum += e; }
        float inv = 1.0f / sum;
        #pragma unroll
        for (int j = 0; j < Ssz; j++) sc[h][i][j] *= inv;
    }
    __syncwarp();

    #pragma unroll
    for (int i = 0; i < Ssz; i++) {
        float s = 0.0f;
        #pragma unroll
        for (int j = 0; j < Ssz; j++) s += sc[h][i][j] * vs[h][j][lane];
        g_ctx[((size_t)(b * Ssz + i)) * REDsz + h * DHsz + lane] = s;
    }
}

// ---------------- orthogonality loss: one block per batch ----------------
__global__ void loss_k()
{
    int b = blockIdx.x, tid = threadIdx.x;
    __shared__ float X[Ssz][REDsz + 1];
    __shared__ float inv[Ssz];
    for (int idx = tid; idx < Ssz * REDsz; idx += 256)
        X[idx >> 8][idx & 255] = g_upd[(size_t)b * Ssz * REDsz + idx];
    __syncthreads();
    int w = tid >> 5, lane = tid & 31;
    for (int r = w; r < Ssz; r += 8) {
        float s = 0.0f;
        for (int d = lane; d < 256; d += 32) s += X[r][d] * X[r][d];
        for (int o = 16; o > 0; o >>= 1) s += __shfl_down_sync(0xffffffffu, s, o);
        if (lane == 0) inv[r] = 1.0f / fmaxf(sqrtf(s), 1e-8f);
    }
    __syncthreads();
    float part = 0.0f;
    if (tid < (Ssz * (Ssz - 1)) / 2) {
        int p = tid, i = 0;
        while (p >= Ssz - 1 - i) { p -= Ssz - 1 - i; i++; }
        int j = i + 1 + p;
        float dot = 0.0f;
        for (int d = 0; d < 256; d++) dot += X[i][d] * X[j][d];
        float gv = fabsf(dot * inv[i] * inv[j]);
        part = fmaxf(gv - 0.1f, 0.0f) * 2.0f;
    }
    __shared__ float red[256];
    red[tid] = part; __syncthreads();
    for (int s = 128; s > 0; s >>= 1) { if (tid < s) red[tid] += red[tid + s]; __syncthreads(); }
    if (tid == 0) atomicAdd(&g_acc, red[0]);
}

// ---------------- logits: mean over S then Wp ----------------
__global__ void logit_k(const float* __restrict__ Wp, const float* __restrict__ bp,
                        float* __restrict__ out, int loff)
{
    int b = blockIdx.x, tid = threadIdx.x;
    __shared__ float mean[REDsz];
    float s = 0.0f;
    for (int ss = 0; ss < Ssz; ss++)
        s += g_upd[((size_t)(b * Ssz + ss)) * REDsz + tid];
    mean[tid] = s * (1.0f / (float)Ssz);
    __syncthreads();
    if (tid < NLAB) {
        float a = bp[tid];
        const float* wr = Wp + tid * REDsz;
        for (int d = 0; d < REDsz; d++) a += mean[d] * wr[d];
        out[loff + b * NLAB + tid] = a;
    }
}

__global__ void fin_k(float* out, int writeloss)
{
    if (writeloss)
        out[0] = g_acc * (1.0f / ((float)Bsz * Ssz * (Ssz - 1)));
}

// ---------------- launch ----------------
extern "C" void kernel_launch(void* const* d_in, const int* in_sizes, int n_in,
                              void* d_out, int out_size)
{
    const float* cls  = (const float*)d_in[0];
    const int*   mask = (const int*)  d_in[1];
    const float* miss = (const float*)d_in[2];
    const float* W1 = (const float*)d_in[3];  const float* b1 = (const float*)d_in[4];
    const float* W2 = (const float*)d_in[5];  const float* b2 = (const float*)d_in[6];
    const float* lg = (const float*)d_in[7];  const float* lb = (const float*)d_in[8];
    const float* Wq = (const float*)d_in[9];  const float* bq = (const float*)d_in[10];
    const float* Wk = (const float*)d_in[11]; const float* bk = (const float*)d_in[12];
    const float* Wv = (const float*)d_in[13]; const float* bv = (const float*)d_in[14];
    const float* Wo = (const float*)d_in[15]; const float* bo = (const float*)d_in[16];
    const float* Wp = (const float*)d_in[17]; const float* bp = (const float*)d_in[18];
    float* out = (float*)d_out;

    int loff = out_size - Bsz * NLAB;
    if (loff < 0) loff = 0;

    float *h1, *h2, *red, *q, *k, *v, *ctx, *upd;
    cudaGetSymbolAddress((void**)&h1,  g_h1);
    cudaGetSymbolAddress((void**)&h2,  g_h2);
    cudaGetSymbolAddress((void**)&red, g_red);
    cudaGetSymbolAddress((void**)&q,   g_q);
    cudaGetSymbolAddress((void**)&k,   g_k);
    cudaGetSymbolAddress((void**)&v,   g_v);
    cudaGetSymbolAddress((void**)&ctx, g_ctx);
    cudaGetSymbolAddress((void**)&upd, g_upd);

    dim3 blk(256);
    // 1) gather + GEMM1 + GELU : [M,768] -> [M,384]
    mmagemm_k<1,1><<<dim3(3, Mrows/128), blk>>>(
        nullptr, W1, nullptr, nullptr, b1, nullptr, nullptr,
        h1, nullptr, nullptr, 384, 768, cls, miss, mask);
    // 2) GEMM2 + GELU : [M,384] -> [M,256]
    mmagemm_k<1,0><<<dim3(2, Mrows/128), blk>>>(
        h1, W2, nullptr, nullptr, b2, nullptr, nullptr,
        h2, nullptr, nullptr, 256, 384, nullptr, nullptr, nullptr);
    // 3) LayerNorm -> g_red (warp per row)
    ln_k<<<Mrows/8, 256>>>(lg, lb);
    // 4) fused QKV projections
    mmagemm_k<0,3><<<dim3(6, Mrows/128), blk>>>(
        red, Wq, Wk, Wv, bq, bk, bv,
        q, k, v, 256, 256, nullptr, nullptr, nullptr);
    // 5) attention (also computes g_use, zeroes g_acc)
    attn_k<<<Bsz, 256>>>(mask);
    // 6) Wo projection + scatter-select epilogue -> g_upd
    mmagemm_k<0,2><<<dim3(2, Mrows/128), blk>>>(
        ctx, Wo, nullptr, nullptr, bo, nullptr, nullptr,
        upd, nullptr, nullptr, 256, 256, nullptr, nullptr, nullptr);
    // 7) orthogonality loss accumulate
    loss_k<<<Bsz, 256>>>();
    // 8) logits
    logit_k<<<Bsz, 256>>>(Wp, bp, out, loff);
    // 9) finalize loss scalar
    fin_k<<<1, 1>>>(out, loff >= 1 ? 1 : 0);
}

// round 10
// speedup vs baseline: 2.3197x; 1.0422x over previous
#include <cuda_runtime.h>
#include <math.h>
#include <stdint.h>

#define Bsz   2048
#define Ssz   23
#define Esz   768
#define REDsz 256
#define Hsz   8
#define DHsz  32
#define NLAB  25
#define Mrows (Bsz*Ssz)   // 47104 = 368*128

// GEMM pipeline config: BK=16, 5 stages
#define STAGES    5
#define ROWSTRIDE 20                    // floats per row (16 + 4 pad) -> 80B
#define ATILE_B   (128*ROWSTRIDE*4)     // 10240 B
#define STAGE_B   (2*ATILE_B)           // A+B = 20480 B
#define SMEM_DYN  (STAGES*STAGE_B)      // 102400 B

// ---------------- scratch (allocation-free) ----------------
__device__ float g_h1 [(size_t)Mrows*384];
__device__ float g_h2 [(size_t)Mrows*256];
__device__ float g_red[(size_t)Mrows*256];
__device__ float g_q  [(size_t)Mrows*256];
__device__ float g_k  [(size_t)Mrows*256];
__device__ float g_v  [(size_t)Mrows*256];
__device__ float g_ctx[(size_t)Mrows*256];
__device__ float g_upd[(size_t)Mrows*256];
__device__ unsigned char g_use[Mrows];
__device__ float g_acc;

__device__ __forceinline__ float gelu_f(float x) {
    return 0.5f * x * (1.0f + erff(x * 0.70710678118654752440f));
}

__device__ __forceinline__ uint32_t smem_u32(const void* p) {
    uint32_t a;
    asm("{ .reg .u64 t; cvta.to.shared.u64 t, %1; cvt.u32.u64 %0, t; }" : "=r"(a) : "l"(p));
    return a;
}

__device__ __forceinline__ uint32_t cvt_tf32(uint32_t x) {
    uint32_t r;
    asm("cvt.rna.tf32.f32 %0, %1;" : "=r"(r) : "f"(__uint_as_float(x)));
    return r;
}

// mma.sync m16n8k8 tf32 (sm_80+ baseline; legal on compute_103)
__device__ __forceinline__ void mma_tf32(float* d, const uint32_t* a, const uint32_t* b) {
    asm volatile(
        "mma.sync.aligned.m16n8k8.row.col.f32.tf32.tf32.f32 "
        "{%0,%1,%2,%3}, {%4,%5,%6,%7}, {%8,%9}, {%0,%1,%2,%3};"
        : "+f"(d[0]), "+f"(d[1]), "+f"(d[2]), "+f"(d[3])
        : "r"(a[0]), "r"(a[1]), "r"(a[2]), "r"(a[3]), "r"(b[0]), "r"(b[1]));
}

#define LDSM_X4(r0_, r1_, r2_, r3_, addr_) \
    asm volatile("ldmatrix.sync.aligned.m8n8.x4.shared.b16 {%0,%1,%2,%3}, [%4];" \
                 : "=r"(r0_), "=r"(r1_), "=r"(r2_), "=r"(r3_) : "r"(addr_))
#define LDSM_X2(r0_, r1_, addr_) \
    asm volatile("ldmatrix.sync.aligned.m8n8.x2.shared.b16 {%0,%1}, [%2];" \
                 : "=r"(r0_), "=r"(r1_) : "r"(addr_))

#define CP_ASYNC16(dst_, src_) \
    asm volatile("cp.async.cg.shared.global [%0], [%1], 16;" :: "r"(dst_), "l"(src_) : "memory")
#define CP_COMMIT() asm volatile("cp.async.commit_group;" ::: "memory")
#define CP_WAIT(n_)  asm volatile("cp.async.wait_group %0;" :: "n"(n_) : "memory")

// ---------------- HMMA tf32 GEMM, cp.async 5-stage pipeline ----------------
// BM=BN=128, BK=16, 256 threads (8 warps), warp tile 64x32 (4 m16 x 4 n8).
// Raw fp32 staged via cp.async; tf32 cvt applied on ldmatrix fragments.
// MODE 0: plain. MODE 1: A gathered from cls/missing by mask (K=Esz).
// MODE 2: epilogue select vs g_red (N=256). MODE 3: fused QKV (grid.x=6).
template<int ACT, int MODE>
__global__ void __launch_bounds__(256, 2) mmagemm_k(
    const float* __restrict__ A,
    const float* __restrict__ Wa, const float* __restrict__ Wb, const float* __restrict__ Wc,
    const float* __restrict__ ba, const float* __restrict__ bb, const float* __restrict__ bc,
    float* __restrict__ Ca, float* __restrict__ Cb, float* __restrict__ Cc,
    int N, int K,
    const float* __restrict__ cls, const float* __restrict__ miss,
    const int* __restrict__ mask)
{
    extern __shared__ char dynS[];

    const int tid  = threadIdx.x;
    const int lane = tid & 31;
    const int wid  = tid >> 5;
    const int g    = lane >> 2;
    const int tg   = lane & 3;
    const int wm   = wid & 1;       // m-half (64 rows)
    const int wn   = wid >> 1;      // n-quarter (32 cols)
    const int bm   = blockIdx.y * 128;

    const float* W; const float* bias; float* C; int bn;
    if (MODE == 3) {
        int sel = blockIdx.x >> 1;
        W    = sel == 0 ? Wa : sel == 1 ? Wb : Wc;
        bias = sel == 0 ? ba : sel == 1 ? bb : bc;
        C    = sel == 0 ? Ca : sel == 1 ? Cb : Cc;
        bn = (blockIdx.x & 1) * 128;
    } else {
        W = Wa; bias = ba; C = Ca;
        bn = blockIdx.x * 128;
    }

    const uint32_t sBase = smem_u32(dynS);

    // ldmatrix per-lane base addresses (within a stage)
    const int lr = lane & 7;
    const int li = lane >> 3;
    const uint32_t aLd = sBase +
        (uint32_t)(((wm * 64 + (li & 1) * 8 + lr) * ROWSTRIDE + (li >> 1) * 4) * 4);
    const uint32_t bLd = sBase + ATILE_B +
        (uint32_t)(((wn * 32 + lr) * ROWSTRIDE + (li & 1) * 4) * 4);

    // staging map: thread -> row (tid>>1), half (tid&1): 8 floats of A and B
    const int srow = tid >> 1;
    const int h8   = (tid & 1) * 8;
    const uint32_t aSt = sBase + (uint32_t)((srow * ROWSTRIDE + h8) * 4);
    const uint32_t bSt = aSt + (uint32_t)ATILE_B;

    const float* Arow;
    if (MODE == 1) {
        int r = bm + srow;
        Arow = (mask[r] > 0) ? (cls + (size_t)r * Esz)
                             : (miss + (size_t)(r % Ssz) * Esz);
    } else {
        Arow = A + (size_t)(bm + srow) * K;
    }
    const float* Brow = W + (size_t)(bn + srow) * K;

    const int nT = K >> 4;   // BK=16

    // prologue: issue tiles 0..STAGES-2
    #pragma unroll
    for (int t = 0; t < STAGES - 1; t++) {
        uint32_t so = (uint32_t)(t * STAGE_B);
        const float* as = Arow + t * 16 + h8;
        const float* bs = Brow + t * 16 + h8;
        CP_ASYNC16(aSt + so,      as);
        CP_ASYNC16(aSt + so + 16, as + 4);
        CP_ASYNC16(bSt + so,      bs);
        CP_ASYNC16(bSt + so + 16, bs + 4);
        CP_COMMIT();
    }

    float acc[4][4][4] = {};
    int cs = 0;                 // consume stage
    int is = STAGES - 1;        // issue stage

    for (int t = 0; t < nT; t++) {
        CP_WAIT(STAGES - 2);
        __syncthreads();

        // refill: tile t+STAGES-1 into stage (t-1)%STAGES (consumed last iter)
        int ft = t + STAGES - 1;
        if (ft < nT) {
            uint32_t so = (uint32_t)(is * STAGE_B);
            const float* as = Arow + ft * 16 + h8;
            const float* bs = Brow + ft * 16 + h8;
            CP_ASYNC16(aSt + so,      as);
            CP_ASYNC16(aSt + so + 16, as + 4);
            CP_ASYNC16(bSt + so,      bs);
            CP_ASYNC16(bSt + so + 16, bs + 4);
        }
        CP_COMMIT();
        if (++is == STAGES) is = 0;

        // MMA on stage cs: 2 k-steps of 8
        const uint32_t so = (uint32_t)(cs * STAGE_B);
        #pragma unroll
        for (int ks = 0; ks < 2; ks++) {
            const uint32_t kOff = so + (uint32_t)(ks * 32);
            uint32_t af[4][4];
            #pragma unroll
            for (int mt = 0; mt < 4; mt++) {
                LDSM_X4(af[mt][0], af[mt][1], af[mt][2], af[mt][3],
                        aLd + (uint32_t)(mt * 16 * ROWSTRIDE * 4) + kOff);
                af[mt][0] = cvt_tf32(af[mt][0]); af[mt][1] = cvt_tf32(af[mt][1]);
                af[mt][2] = cvt_tf32(af[mt][2]); af[mt][3] = cvt_tf32(af[mt][3]);
            }
            uint32_t bf[4][2];
            #pragma unroll
            for (int nt = 0; nt < 4; nt++) {
                LDSM_X2(bf[nt][0], bf[nt][1],
                        bLd + (uint32_t)(nt * 8 * ROWSTRIDE * 4) + kOff);
                bf[nt][0] = cvt_tf32(bf[nt][0]); bf[nt][1] = cvt_tf32(bf[nt][1]);
            }
            #pragma unroll
            for (int mt = 0; mt < 4; mt++)
                #pragma unroll
                for (int nt = 0; nt < 4; nt++)
                    mma_tf32(acc[mt][nt], af[mt], bf[nt]);
        }
        if (++cs == STAGES) cs = 0;
    }

    // epilogue: d0=(g,2tg) d1=(g,2tg+1) d2=(g+8,2tg) d3=(g+8,2tg+1)
    #pragma unroll
    for (int mt = 0; mt < 4; mt++) {
        int m0 = bm + wm * 64 + mt * 16 + g;
        int m1 = m0 + 8;
        bool k0 = true, k1 = true;
        if (MODE == 2) { k0 = g_use[m0] != 0; k1 = g_use[m1] != 0; }
        #pragma unroll
        for (int nt = 0; nt < 4; nt++) {
            int n = bn + wn * 32 + nt * 8 + 2 * tg;
            float2 bz = *reinterpret_cast<const float2*>(bias + n);
            float2 o0, o1;
            o0.x = acc[mt][nt][0] + bz.x; o0.y = acc[mt][nt][1] + bz.y;
            o1.x = acc[mt][nt][2] + bz.x; o1.y = acc[mt][nt][3] + bz.y;
            if (ACT == 1) {
                o0.x = gelu_f(o0.x); o0.y = gelu_f(o0.y);
                o1.x = gelu_f(o1.x); o1.y = gelu_f(o1.y);
            }
            if (MODE == 2) {
                if (!k0) o0 = *reinterpret_cast<const float2*>(&g_red[(size_t)m0 * 256 + n]);
                if (!k1) o1 = *reinterpret_cast<const float2*>(&g_red[(size_t)m1 * 256 + n]);
            }
            *reinterpret_cast<float2*>(&C[(size_t)m0 * N + n]) = o0;
            *reinterpret_cast<float2*>(&C[(size_t)m1 * N + n]) = o1;
        }
    }
}

// ---------------- LayerNorm over 256: one WARP per row ----------------
__global__ void ln_k(const float* __restrict__ gam, const float* __restrict__ bet)
{
    const int wid = threadIdx.x >> 5, lane = threadIdx.x & 31;
    const int r = blockIdx.x * 8 + wid;
    const float* x = &g_h2[(size_t)r * 256 + lane * 8];
    float4 v0 = *reinterpret_cast<const float4*>(x);
    float4 v1 = *reinterpret_cast<const float4*>(x + 4);
    float s = v0.x+v0.y+v0.z+v0.w + v1.x+v1.y+v1.z+v1.w;
    #pragma unroll
    for (int o = 16; o > 0; o >>= 1) s += __shfl_xor_sync(0xffffffffu, s, o);
    float mu = s * (1.0f / 256.0f);
    float d0x=v0.x-mu, d0y=v0.y-mu, d0z=v0.z-mu, d0w=v0.w-mu;
    float d1x=v1.x-mu, d1y=v1.y-mu, d1z=v1.z-mu, d1w=v1.w-mu;
    float sq = d0x*d0x+d0y*d0y+d0z*d0z+d0w*d0w + d1x*d1x+d1y*d1y+d1z*d1z+d1w*d1w;
    #pragma unroll
    for (int o = 16; o > 0; o >>= 1) sq += __shfl_xor_sync(0xffffffffu, sq, o);
    float rs = rsqrtf(sq * (1.0f / 256.0f) + 1e-5f);
    float4 ga0 = *reinterpret_cast<const float4*>(gam + lane * 8);
    float4 ga1 = *reinterpret_cast<const float4*>(gam + lane * 8 + 4);
    float4 be0 = *reinterpret_cast<const float4*>(bet + lane * 8);
    float4 be1 = *reinterpret_cast<const float4*>(bet + lane * 8 + 4);
    float4 o0, o1;
    o0.x = d0x*rs*ga0.x + be0.x; o0.y = d0y*rs*ga0.y + be0.y;
    o0.z = d0z*rs*ga0.z + be0.z; o0.w = d0w*rs*ga0.w + be0.w;
    o1.x = d1x*rs*ga1.x + be1.x; o1.y = d1y*rs*ga1.y + be1.y;
    o1.z = d1z*rs*ga1.z + be1.z; o1.w = d1w*rs*ga1.w + be1.w;
    float* y = &g_red[(size_t)r * 256 + lane * 8];
    *reinterpret_cast<float4*>(y)     = o0;
    *reinterpret_cast<float4*>(y + 4) = o1;
}

// ---------------- attention: one block per batch, warp per head ----------------
__global__ void attn_k(const int* __restrict__ mask)
{
    int b = blockIdx.x, tid = threadIdx.x;
    int h = tid >> 5, lane = tid & 31;
    __shared__ float qs[Hsz][Ssz][33], ks[Hsz][Ssz][33], vs[Hsz][Ssz][33];
    __shared__ float sc[Hsz][Ssz][Ssz + 1];
    __shared__ int exS[Ssz];
    __shared__ int anyS;

    if (b == 0 && tid == 0) g_acc = 0.0f;
    if (tid < Ssz) exS[tid] = (mask[b * Ssz + tid] > 0);
    __syncthreads();
    if (tid == 0) { int a = 0; for (int s = 0; s < Ssz; s++) a |= exS[s]; anyS = a; }
    __syncthreads();
    if (tid < Ssz) g_use[b * Ssz + tid] = (unsigned char)((!exS[tid]) && anyS);

    #pragma unroll
    for (int s = 0; s < Ssz; s++) {
        size_t base = ((size_t)(b * Ssz + s)) * REDsz + h * DHsz + lane;
        qs[h][s][lane] = g_q[base];
        ks[h][s][lane] = g_k[base];
        vs[h][s][lane] = g_v[base];
    }
    __syncwarp();

    for (int idx = lane; idx < Ssz * Ssz; idx += 32) {
        int i = idx / Ssz, j = idx - i * Ssz;
        float dot = 0.0f;
        #pragma unroll
        for (int d = 0; d < 32; d++) dot += qs[h][i][d] * ks[h][j][d];
        sc[h][i][j] = exS[j] ? dot * 0.17677669529663687f : -1e9f;
    }
    __syncwarp();

    if (lane < Ssz) {
        int i = lane;
        float m = -1e30f;
        #pragma unroll
        for (int j = 0; j < Ssz; j++) m = fmaxf(m, sc[h][i][j]);
        float sum = 0.0f;
        #pragma unroll
        for (int j = 0; j < Ssz; j++) { float e = expf(sc[h][i][j] - m); sc[h][i][j] = e; sum += e; }
        float inv = 1.0f / sum;
        #pragma unroll
        for (int j = 0; j < Ssz; j++) sc[h][i][j] *= inv;
    }
    __syncwarp();

    #pragma unroll
    for (int i = 0; i < Ssz; i++) {
        float s = 0.0f;
        #pragma unroll
        for (int j = 0; j < Ssz; j++) s += sc[h][i][j] * vs[h][j][lane];
        g_ctx[((size_t)(b * Ssz + i)) * REDsz + h * DHsz + lane] = s;
    }
}

// ---------------- merged orthogonality loss + logits: one block per batch ----------------
__global__ void losslogit_k(const float* __restrict__ Wp, const float* __restrict__ bp,
                            float* __restrict__ out, int loff)
{
    int b = blockIdx.x, tid = threadIdx.x;
    __shared__ float X[Ssz][REDsz + 1];
    __shared__ float inv[Ssz];
    __shared__ float mean[REDsz];
    for (int idx = tid; idx < Ssz * REDsz; idx += 256)
        X[idx >> 8][idx & 255] = g_upd[(size_t)b * Ssz * REDsz + idx];
    __syncthreads();
    int w = tid >> 5, lane = tid & 31;
    for (int r = w; r < Ssz; r += 8) {
        float s = 0.0f;
        for (int d = lane; d < 256; d += 32) s += X[r][d] * X[r][d];
        for (int o = 16; o > 0; o >>= 1) s += __shfl_down_sync(0xffffffffu, s, o);
        if (lane == 0) inv[r] = 1.0f / fmaxf(sqrtf(s), 1e-8f);
    }
    // column means while norms compute
    {
        float s = 0.0f;
        #pragma unroll
        for (int ss = 0; ss < Ssz; ss++) s += X[ss][tid];
        mean[tid] = s * (1.0f / (float)Ssz);
    }
    __syncthreads();
    float part = 0.0f;
    if (tid < (Ssz * (Ssz - 1)) / 2) {
        int p = tid, i = 0;
        while (p >= Ssz - 1 - i) { p -= Ssz - 1 - i; i++; }
        int j = i + 1 + p;
        float dot = 0.0f;
        for (int d = 0; d < 256; d++) dot += X[i][d] * X[j][d];
        float gv = fabsf(dot * inv[i] * inv[j]);
        part = fmaxf(gv - 0.1f, 0.0f) * 2.0f;
    }
    __shared__ float red[256];
    red[tid] = part; __syncthreads();
    for (int s = 128; s > 0; s >>= 1) { if (tid < s) red[tid] += red[tid + s]; __syncthreads(); }
    if (tid == 0) atomicAdd(&g_acc, red[0]);
    if (tid < NLAB) {
        float a = bp[tid];
        const float* wr = Wp + tid * REDsz;
        for (int d = 0; d < REDsz; d++) a += mean[d] * wr[d];
        out[loff + b * NLAB + tid] = a;
    }
}

__global__ void fin_k(float* out, int writeloss)
{
    if (writeloss)
        out[0] = g_acc * (1.0f / ((float)Bsz * Ssz * (Ssz - 1)));
}

// ---------------- launch ----------------
extern "C" void kernel_launch(void* const* d_in, const int* in_sizes, int n_in,
                              void* d_out, int out_size)
{
    const float* cls  = (const float*)d_in[0];
    const int*   mask = (const int*)  d_in[1];
    const float* miss = (const float*)d_in[2];
    const float* W1 = (const float*)d_in[3];  const float* b1 = (const float*)d_in[4];
    const float* W2 = (const float*)d_in[5];  const float* b2 = (const float*)d_in[6];
    const float* lg = (const float*)d_in[7];  const float* lb = (const float*)d_in[8];
    const float* Wq = (const float*)d_in[9];  const float* bq = (const float*)d_in[10];
    const float* Wk = (const float*)d_in[11]; const float* bk = (const float*)d_in[12];
    const float* Wv = (const float*)d_in[13]; const float* bv = (const float*)d_in[14];
    const float* Wo = (const float*)d_in[15]; const float* bo = (const float*)d_in[16];
    const float* Wp = (const float*)d_in[17]; const float* bp = (const float*)d_in[18];
    float* out = (float*)d_out;

    int loff = out_size - Bsz * NLAB;
    if (loff < 0) loff = 0;

    float *h1, *h2, *red, *q, *k, *v, *ctx, *upd;
    cudaGetSymbolAddress((void**)&h1,  g_h1);
    cudaGetSymbolAddress((void**)&h2,  g_h2);
    cudaGetSymbolAddress((void**)&red, g_red);
    cudaGetSymbolAddress((void**)&q,   g_q);
    cudaGetSymbolAddress((void**)&k,   g_k);
    cudaGetSymbolAddress((void**)&v,   g_v);
    cudaGetSymbolAddress((void**)&ctx, g_ctx);
    cudaGetSymbolAddress((void**)&upd, g_upd);

    // allow >48KB dynamic smem (attribute set is idempotent; not an allocation)
    cudaFuncSetAttribute(mmagemm_k<1,1>, cudaFuncAttributeMaxDynamicSharedMemorySize, SMEM_DYN);
    cudaFuncSetAttribute(mmagemm_k<1,0>, cudaFuncAttributeMaxDynamicSharedMemorySize, SMEM_DYN);
    cudaFuncSetAttribute(mmagemm_k<0,3>, cudaFuncAttributeMaxDynamicSharedMemorySize, SMEM_DYN);
    cudaFuncSetAttribute(mmagemm_k<0,2>, cudaFuncAttributeMaxDynamicSharedMemorySize, SMEM_DYN);

    dim3 blk(256);
    // 1) gather + GEMM1 + GELU : [M,768] -> [M,384]
    mmagemm_k<1,1><<<dim3(3, Mrows/128), blk, SMEM_DYN>>>(
        nullptr, W1, nullptr, nullptr, b1, nullptr, nullptr,
        h1, nullptr, nullptr, 384, 768, cls, miss, mask);
    // 2) GEMM2 + GELU : [M,384] -> [M,256]
    mmagemm_k<1,0><<<dim3(2, Mrows/128), blk, SMEM_DYN>>>(
        h1, W2, nullptr, nullptr, b2, nullptr, nullptr,
        h2, nullptr, nullptr, 256, 384, nullptr, nullptr, nullptr);
    // 3) LayerNorm -> g_red (warp per row)
    ln_k<<<Mrows/8, 256>>>(lg, lb);
    // 4) fused QKV projections
    mmagemm_k<0,3><<<dim3(6, Mrows/128), blk, SMEM_DYN>>>(
        red, Wq, Wk, Wv, bq, bk, bv,
        q, k, v, 256, 256, nullptr, nullptr, nullptr);
    // 5) attention (also computes g_use, zeroes g_acc)
    attn_k<<<Bsz, 256>>>(mask);
    // 6) Wo projection + scatter-select epilogue -> g_upd
    mmagemm_k<0,2><<<dim3(2, Mrows/128), blk, SMEM_DYN>>>(
        ctx, Wo, nullptr, nullptr, bo, nullptr, nullptr,
        upd, nullptr, nullptr, 256, 256, nullptr, nullptr, nullptr);
    // 7) merged orthogonality loss + logits
    losslogit_k<<<Bsz, 256>>>(Wp, bp, out, loff);
    // 8) finalize loss scalar
    fin_k<<<1, 1>>>(out, loff >= 1 ? 1 : 0);
}

// round 11
// speedup vs baseline: 2.4031x; 1.0359x over previous
#include <cuda_runtime.h>
#include <math.h>
#include <stdint.h>

#define Bsz   2048
#define Ssz   23
#define Esz   768
#define REDsz 256
#define Hsz   8
#define DHsz  32
#define NLAB  25
#define Mrows (Bsz*Ssz)   // 47104 = 368*128

// GEMM pipeline config: BK=16, 5 stages
#define STAGES    5
#define ROWSTRIDE 20                    // floats per row (16 + 4 pad) -> 80B
#define ATILE_B   (128*ROWSTRIDE*4)     // 10240 B
#define STAGE_B   (2*ATILE_B)           // A+B = 20480 B
#define SMEM_DYN  (STAGES*STAGE_B)      // 102400 B

// rounded-weight scratch offsets (floats)
#define W1N  (384*768)
#define W2N  (256*384)
#define WQN  (256*256)
#define OFF_W1 0
#define OFF_W2 (OFF_W1 + W1N)
#define OFF_WQ (OFF_W2 + W2N)
#define OFF_WK (OFF_WQ + WQN)
#define OFF_WV (OFF_WK + WQN)
#define OFF_WO (OFF_WV + WQN)
#define WTOT   (OFF_WO + WQN)

// ---------------- scratch (allocation-free) ----------------
__device__ float g_h1  [(size_t)Mrows*384];
__device__ float g_h2  [(size_t)Mrows*256];
__device__ float g_red [(size_t)Mrows*256];   // fp32 (select path)
__device__ float g_redr[(size_t)Mrows*256];   // tf32-rounded (QKV A input)
__device__ float g_q  [(size_t)Mrows*256];
__device__ float g_k  [(size_t)Mrows*256];
__device__ float g_v  [(size_t)Mrows*256];
__device__ float g_ctx[(size_t)Mrows*256];
__device__ float g_upd[(size_t)Mrows*256];
__device__ float g_w  [WTOT];
__device__ unsigned char g_use[Mrows];
__device__ float g_acc;

__device__ __forceinline__ float gelu_f(float x) {
    return 0.5f * x * (1.0f + erff(x * 0.70710678118654752440f));
}

__device__ __forceinline__ uint32_t smem_u32(const void* p) {
    uint32_t a;
    asm("{ .reg .u64 t; cvta.to.shared.u64 t, %1; cvt.u32.u64 %0, t; }" : "=r"(a) : "l"(p));
    return a;
}

__device__ __forceinline__ uint32_t cvt_tf32(uint32_t x) {
    uint32_t r;
    asm("cvt.rna.tf32.f32 %0, %1;" : "=r"(r) : "f"(__uint_as_float(x)));
    return r;
}
__device__ __forceinline__ float tf32f(float x) {
    uint32_t r;
    asm("cvt.rna.tf32.f32 %0, %1;" : "=r"(r) : "f"(x));
    return __uint_as_float(r);
}

// mma.sync m16n8k8 tf32 (sm_80+ baseline; legal on compute_103)
__device__ __forceinline__ void mma_tf32(float* d, const uint32_t* a, const uint32_t* b) {
    asm volatile(
        "mma.sync.aligned.m16n8k8.row.col.f32.tf32.tf32.f32 "
        "{%0,%1,%2,%3}, {%4,%5,%6,%7}, {%8,%9}, {%0,%1,%2,%3};"
        : "+f"(d[0]), "+f"(d[1]), "+f"(d[2]), "+f"(d[3])
        : "r"(a[0]), "r"(a[1]), "r"(a[2]), "r"(a[3]), "r"(b[0]), "r"(b[1]));
}

#define LDSM_X4(r0_, r1_, r2_, r3_, addr_) \
    asm volatile("ldmatrix.sync.aligned.m8n8.x4.shared.b16 {%0,%1,%2,%3}, [%4];" \
                 : "=r"(r0_), "=r"(r1_), "=r"(r2_), "=r"(r3_) : "r"(addr_))
#define LDSM_X2(r0_, r1_, addr_) \
    asm volatile("ldmatrix.sync.aligned.m8n8.x2.shared.b16 {%0,%1}, [%2];" \
                 : "=r"(r0_), "=r"(r1_) : "r"(addr_))

#define CP_ASYNC16(dst_, src_) \
    asm volatile("cp.async.cg.shared.global [%0], [%1], 16;" :: "r"(dst_), "l"(src_) : "memory")
#define CP_COMMIT() asm volatile("cp.async.commit_group;" ::: "memory")
#define CP_WAIT(n_)  asm volatile("cp.async.wait_group %0;" :: "n"(n_) : "memory")

// ---------------- weight prep: tf32-round all weight matrices ----------------
__global__ void wprep_k(const float* __restrict__ W1, const float* __restrict__ W2,
                        const float* __restrict__ Wq, const float* __restrict__ Wk,
                        const float* __restrict__ Wv, const float* __restrict__ Wo)
{
    int i = blockIdx.x * 256 + threadIdx.x;
    if (i >= WTOT) return;
    float v;
    if      (i < OFF_W2) v = W1[i - OFF_W1];
    else if (i < OFF_WQ) v = W2[i - OFF_W2];
    else if (i < OFF_WK) v = Wq[i - OFF_WQ];
    else if (i < OFF_WV) v = Wk[i - OFF_WK];
    else if (i < OFF_WO) v = Wv[i - OFF_WV];
    else                 v = Wo[i - OFF_WO];
    g_w[i] = tf32f(v);
}

// ---------------- HMMA tf32 GEMM, cp.async 5-stage pipeline ----------------
// BM=BN=128, BK=16, 256 threads (8 warps), warp tile 64x32 (4 m16 x 4 n8).
// Weights pre-rounded (no B cvt). A pre-rounded except MODE 1 (CVTA=1).
// MODE 0: plain. MODE 1: A gathered from cls/missing by mask (K=Esz).
// MODE 2: epilogue select vs g_red (N=256). MODE 3: fused QKV (grid.x=6).
// ROUT: store tf32-rounded output (GEMM1 -> g_h1, consumed only as GEMM A).
template<int ACT, int MODE, int CVTA, int ROUT>
__global__ void __launch_bounds__(256, 2) mmagemm_k(
    const float* __restrict__ A,
    const float* __restrict__ Wa, const float* __restrict__ Wb, const float* __restrict__ Wc,
    const float* __restrict__ ba, const float* __restrict__ bb, const float* __restrict__ bc,
    float* __restrict__ Ca, float* __restrict__ Cb, float* __restrict__ Cc,
    int N, int K,
    const float* __restrict__ cls, const float* __restrict__ miss,
    const int* __restrict__ mask)
{
    extern __shared__ char dynS[];

    const int tid  = threadIdx.x;
    const int lane = tid & 31;
    const int wid  = tid >> 5;
    const int g    = lane >> 2;
    const int tg   = lane & 3;
    const int wm   = wid & 1;       // m-half (64 rows)
    const int wn   = wid >> 1;      // n-quarter (32 cols)
    const int bm   = blockIdx.y * 128;

    const float* W; const float* bias; float* C; int bn;
    if (MODE == 3) {
        int sel = blockIdx.x >> 1;
        W    = sel == 0 ? Wa : sel == 1 ? Wb : Wc;
        bias = sel == 0 ? ba : sel == 1 ? bb : bc;
        C    = sel == 0 ? Ca : sel == 1 ? Cb : Cc;
        bn = (blockIdx.x & 1) * 128;
    } else {
        W = Wa; bias = ba; C = Ca;
        bn = blockIdx.x * 128;
    }

    const uint32_t sBase = smem_u32(dynS);

    // ldmatrix per-lane base addresses (within a stage)
    const int lr = lane & 7;
    const int li = lane >> 3;
    const uint32_t aLd = sBase +
        (uint32_t)(((wm * 64 + (li & 1) * 8 + lr) * ROWSTRIDE + (li >> 1) * 4) * 4);
    const uint32_t bLd = sBase + ATILE_B +
        (uint32_t)(((wn * 32 + lr) * ROWSTRIDE + (li & 1) * 4) * 4);

    // staging map: thread -> row (tid>>1), half (tid&1): 8 floats of A and B
    const int srow = tid >> 1;
    const int h8   = (tid & 1) * 8;
    const uint32_t aSt = sBase + (uint32_t)((srow * ROWSTRIDE + h8) * 4);
    const uint32_t bSt = aSt + (uint32_t)ATILE_B;

    const float* Arow;
    if (MODE == 1) {
        int r = bm + srow;
        Arow = (mask[r] > 0) ? (cls + (size_t)r * Esz)
                             : (miss + (size_t)(r % Ssz) * Esz);
    } else {
        Arow = A + (size_t)(bm + srow) * K;
    }
    const float* Brow = W + (size_t)(bn + srow) * K;

    const int nT = K >> 4;   // BK=16

    // prologue: issue tiles 0..STAGES-2
    #pragma unroll
    for (int t = 0; t < STAGES - 1; t++) {
        uint32_t so = (uint32_t)(t * STAGE_B);
        const float* as = Arow + t * 16 + h8;
        const float* bs = Brow + t * 16 + h8;
        CP_ASYNC16(aSt + so,      as);
        CP_ASYNC16(aSt + so + 16, as + 4);
        CP_ASYNC16(bSt + so,      bs);
        CP_ASYNC16(bSt + so + 16, bs + 4);
        CP_COMMIT();
    }

    float acc[4][4][4] = {};
    int cs = 0;                 // consume stage
    int is = STAGES - 1;        // issue stage

    for (int t = 0; t < nT; t++) {
        CP_WAIT(STAGES - 2);
        __syncthreads();

        // refill: tile t+STAGES-1 into stage (t-1)%STAGES (consumed last iter)
        int ft = t + STAGES - 1;
        if (ft < nT) {
            uint32_t so = (uint32_t)(is * STAGE_B);
            const float* as = Arow + ft * 16 + h8;
            const float* bs = Brow + ft * 16 + h8;
            CP_ASYNC16(aSt + so,      as);
            CP_ASYNC16(aSt + so + 16, as + 4);
            CP_ASYNC16(bSt + so,      bs);
            CP_ASYNC16(bSt + so + 16, bs + 4);
        }
        CP_COMMIT();
        if (++is == STAGES) is = 0;

        // MMA on stage cs: 2 k-steps of 8
        const uint32_t so = (uint32_t)(cs * STAGE_B);
        #pragma unroll
        for (int ks = 0; ks < 2; ks++) {
            const uint32_t kOff = so + (uint32_t)(ks * 32);
            uint32_t af[4][4];
            #pragma unroll
            for (int mt = 0; mt < 4; mt++) {
                LDSM_X4(af[mt][0], af[mt][1], af[mt][2], af[mt][3],
                        aLd + (uint32_t)(mt * 16 * ROWSTRIDE * 4) + kOff);
                if (CVTA) {
                    af[mt][0] = cvt_tf32(af[mt][0]); af[mt][1] = cvt_tf32(af[mt][1]);
                    af[mt][2] = cvt_tf32(af[mt][2]); af[mt][3] = cvt_tf32(af[mt][3]);
                }
            }
            uint32_t bf[4][2];
            #pragma unroll
            for (int nt = 0; nt < 4; nt++)
                LDSM_X2(bf[nt][0], bf[nt][1],
                        bLd + (uint32_t)(nt * 8 * ROWSTRIDE * 4) + kOff);
            #pragma unroll
            for (int mt = 0; mt < 4; mt++)
                #pragma unroll
                for (int nt = 0; nt < 4; nt++)
                    mma_tf32(acc[mt][nt], af[mt], bf[nt]);
        }
        if (++cs == STAGES) cs = 0;
    }

    // epilogue: d0=(g,2tg) d1=(g,2tg+1) d2=(g+8,2tg) d3=(g+8,2tg+1)
    #pragma unroll
    for (int mt = 0; mt < 4; mt++) {
        int m0 = bm + wm * 64 + mt * 16 + g;
        int m1 = m0 + 8;
        bool k0 = true, k1 = true;
        if (MODE == 2) { k0 = g_use[m0] != 0; k1 = g_use[m1] != 0; }
        #pragma unroll
        for (int nt = 0; nt < 4; nt++) {
            int n = bn + wn * 32 + nt * 8 + 2 * tg;
            float2 bz = *reinterpret_cast<const float2*>(bias + n);
            float2 o0, o1;
            o0.x = acc[mt][nt][0] + bz.x; o0.y = acc[mt][nt][1] + bz.y;
            o1.x = acc[mt][nt][2] + bz.x; o1.y = acc[mt][nt][3] + bz.y;
            if (ACT == 1) {
                o0.x = gelu_f(o0.x); o0.y = gelu_f(o0.y);
                o1.x = gelu_f(o1.x); o1.y = gelu_f(o1.y);
            }
            if (ROUT) {
                o0.x = tf32f(o0.x); o0.y = tf32f(o0.y);
                o1.x = tf32f(o1.x); o1.y = tf32f(o1.y);
            }
            if (MODE == 2) {
                if (!k0) o0 = *reinterpret_cast<const float2*>(&g_red[(size_t)m0 * 256 + n]);
                if (!k1) o1 = *reinterpret_cast<const float2*>(&g_red[(size_t)m1 * 256 + n]);
            }
            *reinterpret_cast<float2*>(&C[(size_t)m0 * N + n]) = o0;
            *reinterpret_cast<float2*>(&C[(size_t)m1 * N + n]) = o1;
        }
    }
}

// ---------------- LayerNorm over 256: one WARP per row, dual store ----------------
__global__ void ln_k(const float* __restrict__ gam, const float* __restrict__ bet)
{
    const int wid = threadIdx.x >> 5, lane = threadIdx.x & 31;
    const int r = blockIdx.x * 8 + wid;
    const float* x = &g_h2[(size_t)r * 256 + lane * 8];
    float4 v0 = *reinterpret_cast<const float4*>(x);
    float4 v1 = *reinterpret_cast<const float4*>(x + 4);
    float s = v0.x+v0.y+v0.z+v0.w + v1.x+v1.y+v1.z+v1.w;
    #pragma unroll
    for (int o = 16; o > 0; o >>= 1) s += __shfl_xor_sync(0xffffffffu, s, o);
    float mu = s * (1.0f / 256.0f);
    float d0x=v0.x-mu, d0y=v0.y-mu, d0z=v0.z-mu, d0w=v0.w-mu;
    float d1x=v1.x-mu, d1y=v1.y-mu, d1z=v1.z-mu, d1w=v1.w-mu;
    float sq = d0x*d0x+d0y*d0y+d0z*d0z+d0w*d0w + d1x*d1x+d1y*d1y+d1z*d1z+d1w*d1w;
    #pragma unroll
    for (int o = 16; o > 0; o >>= 1) sq += __shfl_xor_sync(0xffffffffu, sq, o);
    float rs = rsqrtf(sq * (1.0f / 256.0f) + 1e-5f);
    float4 ga0 = *reinterpret_cast<const float4*>(gam + lane * 8);
    float4 ga1 = *reinterpret_cast<const float4*>(gam + lane * 8 + 4);
    float4 be0 = *reinterpret_cast<const float4*>(bet + lane * 8);
    float4 be1 = *reinterpret_cast<const float4*>(bet + lane * 8 + 4);
    float4 o0, o1;
    o0.x = d0x*rs*ga0.x + be0.x; o0.y = d0y*rs*ga0.y + be0.y;
    o0.z = d0z*rs*ga0.z + be0.z; o0.w = d0w*rs*ga0.w + be0.w;
    o1.x = d1x*rs*ga1.x + be1.x; o1.y = d1y*rs*ga1.y + be1.y;
    o1.z = d1z*rs*ga1.z + be1.z; o1.w = d1w*rs*ga1.w + be1.w;
    float* y = &g_red[(size_t)r * 256 + lane * 8];
    *reinterpret_cast<float4*>(y)     = o0;
    *reinterpret_cast<float4*>(y + 4) = o1;
    float4 r0, r1;
    r0.x = tf32f(o0.x); r0.y = tf32f(o0.y); r0.z = tf32f(o0.z); r0.w = tf32f(o0.w);
    r1.x = tf32f(o1.x); r1.y = tf32f(o1.y); r1.z = tf32f(o1.z); r1.w = tf32f(o1.w);
    float* yr = &g_redr[(size_t)r * 256 + lane * 8];
    *reinterpret_cast<float4*>(yr)     = r0;
    *reinterpret_cast<float4*>(yr + 4) = r1;
}

// ---------------- attention: one block per batch, warp per head ----------------
__global__ void attn_k(const int* __restrict__ mask)
{
    int b = blockIdx.x, tid = threadIdx.x;
    int h = tid >> 5, lane = tid & 31;
    __shared__ float qs[Hsz][Ssz][33], ks[Hsz][Ssz][33], vs[Hsz][Ssz][33];
    __shared__ float sc[Hsz][Ssz][Ssz + 1];
    __shared__ int exS[Ssz];
    __shared__ int anyS;

    if (b == 0 && tid == 0) g_acc = 0.0f;
    if (tid < Ssz) exS[tid] = (mask[b * Ssz + tid] > 0);
    __syncthreads();
    if (tid == 0) { int a = 0; for (int s = 0; s < Ssz; s++) a |= exS[s]; anyS = a; }
    __syncthreads();
    if (tid < Ssz) g_use[b * Ssz + tid] = (unsigned char)((!exS[tid]) && anyS);

    #pragma unroll
    for (int s = 0; s < Ssz; s++) {
        size_t base = ((size_t)(b * Ssz + s)) * REDsz + h * DHsz + lane;
        qs[h][s][lane] = g_q[base];
        ks[h][s][lane] = g_k[base];
        vs[h][s][lane] = g_v[base];
    }
    __syncwarp();

    for (int idx = lane; idx < Ssz * Ssz; idx += 32) {
        int i = idx / Ssz, j = idx - i * Ssz;
        float dot = 0.0f;
        #pragma unroll
        for (int d = 0; d < 32; d++) dot += qs[h][i][d] * ks[h][j][d];
        sc[h][i][j] = exS[j] ? dot * 0.17677669529663687f : -1e9f;
    }
    __syncwarp();

    if (lane < Ssz) {
        int i = lane;
        float m = -1e30f;
        #pragma unroll
        for (int j = 0; j < Ssz; j++) m = fmaxf(m, sc[h][i][j]);
        float sum = 0.0f;
        #pragma unroll
        for (int j = 0; j < Ssz; j++) { float e = expf(sc[h][i][j] - m); sc[h][i][j] = e; sum += e; }
        float inv = 1.0f / sum;
        #pragma unroll
        for (int j = 0; j < Ssz; j++) sc[h][i][j] *= inv;
    }
    __syncwarp();

    #pragma unroll
    for (int i = 0; i < Ssz; i++) {
        float s = 0.0f;
        #pragma unroll
        for (int j = 0; j < Ssz; j++) s += sc[h][i][j] * vs[h][j][lane];
        g_ctx[((size_t)(b * Ssz + i)) * REDsz + h * DHsz + lane] = tf32f(s);
    }
}

// ---------------- merged orthogonality loss + logits: one block per batch ----------------
__global__ void losslogit_k(const float* __restrict__ Wp, const float* __restrict__ bp,
                            float* __restrict__ out, int loff)
{
    int b = blockIdx.x, tid = threadIdx.x;
    __shared__ float X[Ssz][REDsz + 1];
    __shared__ float inv[Ssz];
    __shared__ float mean[REDsz];
    for (int idx = tid; idx < Ssz * REDsz; idx += 256)
        X[idx >> 8][idx & 255] = g_upd[(size_t)b * Ssz * REDsz + idx];
    __syncthreads();
    int w = tid >> 5, lane = tid & 31;
    for (int r = w; r < Ssz; r += 8) {
        float s = 0.0f;
        for (int d = lane; d < 256; d += 32) s += X[r][d] * X[r][d];
        for (int o = 16; o > 0; o >>= 1) s += __shfl_down_sync(0xffffffffu, s, o);
        if (lane == 0) inv[r] = 1.0f / fmaxf(sqrtf(s), 1e-8f);
    }
    {
        float s = 0.0f;
        #pragma unroll
        for (int ss = 0; ss < Ssz; ss++) s += X[ss][tid];
        mean[tid] = s * (1.0f / (float)Ssz);
    }
    __syncthreads();
    float part = 0.0f;
    if (tid < (Ssz * (Ssz - 1)) / 2) {
        int p = tid, i = 0;
        while (p >= Ssz - 1 - i) { p -= Ssz - 1 - i; i++; }
        int j = i + 1 + p;
        float dot = 0.0f;
        for (int d = 0; d < 256; d++) dot += X[i][d] * X[j][d];
        float gv = fabsf(dot * inv[i] * inv[j]);
        part = fmaxf(gv - 0.1f, 0.0f) * 2.0f;
    }
    __shared__ float red[256];
    red[tid] = part; __syncthreads();
    for (int s = 128; s > 0; s >>= 1) { if (tid < s) red[tid] += red[tid + s]; __syncthreads(); }
    if (tid == 0) atomicAdd(&g_acc, red[0]);
    if (tid < NLAB) {
        float a = bp[tid];
        const float* wr = Wp + tid * REDsz;
        for (int d = 0; d < REDsz; d++) a += mean[d] * wr[d];
        out[loff + b * NLAB + tid] = a;
    }
}

__global__ void fin_k(float* out, int writeloss)
{
    if (writeloss)
        out[0] = g_acc * (1.0f / ((float)Bsz * Ssz * (Ssz - 1)));
}

// ---------------- launch ----------------
extern "C" void kernel_launch(void* const* d_in, const int* in_sizes, int n_in,
                              void* d_out, int out_size)
{
    const float* cls  = (const float*)d_in[0];
    const int*   mask = (const int*)  d_in[1];
    const float* miss = (const float*)d_in[2];
    const float* W1 = (const float*)d_in[3];  const float* b1 = (const float*)d_in[4];
    const float* W2 = (const float*)d_in[5];  const float* b2 = (const float*)d_in[6];
    const float* lg = (const float*)d_in[7];  const float* lb = (const float*)d_in[8];
    const float* Wq = (const float*)d_in[9];  const float* bq = (const float*)d_in[10];
    const float* Wk = (const float*)d_in[11]; const float* bk = (const float*)d_in[12];
    const float* Wv = (const float*)d_in[13]; const float* bv = (const float*)d_in[14];
    const float* Wo = (const float*)d_in[15]; const float* bo = (const float*)d_in[16];
    const float* Wp = (const float*)d_in[17]; const float* bp = (const float*)d_in[18];
    float* out = (float*)d_out;

    int loff = out_size - Bsz * NLAB;
    if (loff < 0) loff = 0;

    float *h1, *h2, *red, *redr, *q, *k, *v, *ctx, *upd, *wbuf;
    cudaGetSymbolAddress((void**)&h1,   g_h1);
    cudaGetSymbolAddress((void**)&h2,   g_h2);
    cudaGetSymbolAddress((void**)&red,  g_red);
    cudaGetSymbolAddress((void**)&redr, g_redr);
    cudaGetSymbolAddress((void**)&q,    g_q);
    cudaGetSymbolAddress((void**)&k,    g_k);
    cudaGetSymbolAddress((void**)&v,    g_v);
    cudaGetSymbolAddress((void**)&ctx,  g_ctx);
    cudaGetSymbolAddress((void**)&upd,  g_upd);
    cudaGetSymbolAddress((void**)&wbuf, g_w);

    cudaFuncSetAttribute(mmagemm_k<1,1,1,1>, cudaFuncAttributeMaxDynamicSharedMemorySize, SMEM_DYN);
    cudaFuncSetAttribute(mmagemm_k<1,0,0,0>, cudaFuncAttributeMaxDynamicSharedMemorySize, SMEM_DYN);
    cudaFuncSetAttribute(mmagemm_k<0,3,0,0>, cudaFuncAttributeMaxDynamicSharedMemorySize, SMEM_DYN);
    cudaFuncSetAttribute(mmagemm_k<0,2,0,0>, cudaFuncAttributeMaxDynamicSharedMemorySize, SMEM_DYN);

    dim3 blk(256);
    // 0) round all weights to tf32 once
    wprep_k<<<(WTOT + 255) / 256, 256>>>(W1, W2, Wq, Wk, Wv, Wo);
    // 1) gather + GEMM1 + GELU (rounded out) : [M,768] -> [M,384]
    mmagemm_k<1,1,1,1><<<dim3(3, Mrows/128), blk, SMEM_DYN>>>(
        nullptr, wbuf + OFF_W1, nullptr, nullptr, b1, nullptr, nullptr,
        h1, nullptr, nullptr, 384, 768, cls, miss, mask);
    // 2) GEMM2 + GELU : [M,384] -> [M,256]  (A pre-rounded)
    mmagemm_k<1,0,0,0><<<dim3(2, Mrows/128), blk, SMEM_DYN>>>(
        h1, wbuf + OFF_W2, nullptr, nullptr, b2, nullptr, nullptr,
        h2, nullptr, nullptr, 256, 384, nullptr, nullptr, nullptr);
    // 3) LayerNorm -> g_red (fp32) + g_redr (rounded)
    ln_k<<<Mrows/8, 256>>>(lg, lb);
    // 4) fused QKV projections (A = rounded red)
    mmagemm_k<0,3,0,0><<<dim3(6, Mrows/128), blk, SMEM_DYN>>>(
        redr, wbuf + OFF_WQ, wbuf + OFF_WK, wbuf + OFF_WV, bq, bk, bv,
        q, k, v, 256, 256, nullptr, nullptr, nullptr);
    // 5) attention (writes rounded ctx, computes g_use, zeroes g_acc)
    attn_k<<<Bsz, 256>>>(mask);
    // 6) Wo projection + scatter-select epilogue -> g_upd
    mmagemm_k<0,2,0,0><<<dim3(2, Mrows/128), blk, SMEM_DYN>>>(
        ctx, wbuf + OFF_WO, nullptr, nullptr, bo, nullptr, nullptr,
        upd, nullptr, nullptr, 256, 256, nullptr, nullptr, nullptr);
    // 7) merged orthogonality loss + logits
    losslogit_k<<<Bsz, 256>>>(Wp, bp, out, loff);
    // 8) finalize loss scalar
    fin_k<<<1, 1>>>(out, loff >= 1 ? 1 : 0);
}

// round 12
// speedup vs baseline: 3.2426x; 1.3493x over previous
#include <cuda_runtime.h>
#include <cuda_fp16.h>
#include <math.h>
#include <stdint.h>

#define Bsz   2048
#define Ssz   23
#define Esz   768
#define REDsz 256
#define Hsz   8
#define DHsz  32
#define NLAB  25
#define Mrows (Bsz*Ssz)   // 47104 = 368*128

// GEMM pipeline config: fp16, BK=32, 5 stages
#define STAGES    5
#define ROWB      80                    // bytes per smem row (64 data + 16 pad)
#define ATILE_B   (128*ROWB)            // 10240 B
#define STAGE_B   (2*ATILE_B)           // 20480 B
#define SMEM_DYN  (STAGES*STAGE_B)      // 102400 B

// fp16 weight scratch offsets (halves)
#define W1N  (384*768)
#define W2N  (256*384)
#define WQN  (256*256)
#define OFF_W1 0
#define OFF_W2 (OFF_W1 + W1N)
#define OFF_WQ (OFF_W2 + W2N)
#define OFF_WK (OFF_WQ + WQN)
#define OFF_WV (OFF_WK + WQN)
#define OFF_WO (OFF_WV + WQN)
#define WTOT   (OFF_WO + WQN)

// ---------------- scratch (allocation-free) ----------------
__device__ __half g_ah [(size_t)Mrows*768];   // gathered+converted GEMM1 A
__device__ __half g_h1h[(size_t)Mrows*384];   // GEMM1 out (fp16, GEMM2 A)
__device__ float  g_h2 [(size_t)Mrows*256];
__device__ float  g_red [(size_t)Mrows*256];  // fp32 (select path)
__device__ __half g_redh[(size_t)Mrows*256];  // fp16 (QKV A)
__device__ float  g_q  [(size_t)Mrows*256];
__device__ float  g_k  [(size_t)Mrows*256];
__device__ float  g_v  [(size_t)Mrows*256];
__device__ __half g_ctxh[(size_t)Mrows*256];  // fp16 (Wo A)
__device__ float  g_upd[(size_t)Mrows*256];
__device__ __half g_wh [WTOT];
__device__ unsigned char g_use[Mrows];
__device__ float g_acc;

__device__ __forceinline__ float gelu_f(float x) {
    return 0.5f * x * (1.0f + erff(x * 0.70710678118654752440f));
}

__device__ __forceinline__ uint32_t smem_u32(const void* p) {
    uint32_t a;
    asm("{ .reg .u64 t; cvta.to.shared.u64 t, %1; cvt.u32.u64 %0, t; }" : "=r"(a) : "l"(p));
    return a;
}

// mma.sync m16n8k16 fp16 -> fp32 accum (sm_80+ baseline; legal on compute_103)
__device__ __forceinline__ void mma_f16(float* d, const uint32_t* a, const uint32_t* b) {
    asm volatile(
        "mma.sync.aligned.m16n8k16.row.col.f32.f16.f16.f32 "
        "{%0,%1,%2,%3}, {%4,%5,%6,%7}, {%8,%9}, {%0,%1,%2,%3};"
        : "+f"(d[0]), "+f"(d[1]), "+f"(d[2]), "+f"(d[3])
        : "r"(a[0]), "r"(a[1]), "r"(a[2]), "r"(a[3]), "r"(b[0]), "r"(b[1]));
}

#define LDSM_X4(r0_, r1_, r2_, r3_, addr_) \
    asm volatile("ldmatrix.sync.aligned.m8n8.x4.shared.b16 {%0,%1,%2,%3}, [%4];" \
                 : "=r"(r0_), "=r"(r1_), "=r"(r2_), "=r"(r3_) : "r"(addr_))
#define LDSM_X2(r0_, r1_, addr_) \
    asm volatile("ldmatrix.sync.aligned.m8n8.x2.shared.b16 {%0,%1}, [%2];" \
                 : "=r"(r0_), "=r"(r1_) : "r"(addr_))

#define CP_ASYNC16(dst_, src_) \
    asm volatile("cp.async.cg.shared.global [%0], [%1], 16;" :: "r"(dst_), "l"(src_) : "memory")
#define CP_COMMIT() asm volatile("cp.async.commit_group;" ::: "memory")
#define CP_WAIT(n_)  asm volatile("cp.async.wait_group %0;" :: "n"(n_) : "memory")

// ---------------- prep: gather GEMM1 A + convert to fp16 ----------------
__global__ void gprep_k(const float* __restrict__ cls, const float* __restrict__ miss,
                        const int* __restrict__ mask)
{
    int i = blockIdx.x * 256 + threadIdx.x;          // one float4 per thread
    if (i >= Mrows * (Esz / 4)) return;
    int r = i / (Esz / 4);
    int c = (i - r * (Esz / 4)) * 4;
    const float* src = (mask[r] > 0) ? (cls + (size_t)r * Esz)
                                     : (miss + (size_t)(r % Ssz) * Esz);
    float4 v = *reinterpret_cast<const float4*>(src + c);
    __half2 h0 = __floats2half2_rn(v.x, v.y);
    __half2 h1 = __floats2half2_rn(v.z, v.w);
    uint2 o;
    o.x = *reinterpret_cast<uint32_t*>(&h0);
    o.y = *reinterpret_cast<uint32_t*>(&h1);
    *reinterpret_cast<uint2*>(&g_ah[(size_t)r * Esz + c]) = o;
}

// ---------------- prep: weights -> fp16 ----------------
__global__ void wprep_k(const float* __restrict__ W1, const float* __restrict__ W2,
                        const float* __restrict__ Wq, const float* __restrict__ Wk,
                        const float* __restrict__ Wv, const float* __restrict__ Wo)
{
    int i = blockIdx.x * 256 + threadIdx.x;
    if (i >= WTOT) return;
    float v;
    if      (i < OFF_W2) v = W1[i - OFF_W1];
    else if (i < OFF_WQ) v = W2[i - OFF_W2];
    else if (i < OFF_WK) v = Wq[i - OFF_WQ];
    else if (i < OFF_WV) v = Wk[i - OFF_WK];
    else if (i < OFF_WO) v = Wv[i - OFF_WV];
    else                 v = Wo[i - OFF_WO];
    g_wh[i] = __float2half_rn(v);
}

// ---------------- HMMA fp16 GEMM, cp.async 5-stage pipeline ----------------
// BM=BN=128, BK=32 (halves), 256 threads (8 warps), warp tile 64x32.
// Per k-tile per warp: 8 LDSM_X4(A) + 8 LDSM_X2(B) + 32 mma.m16n8k16.
// MODE 0: plain. MODE 2: epilogue select vs g_red (N=256). MODE 3: fused QKV.
// OUTH: store fp16 output (GEMM1 -> g_h1h).
template<int ACT, int MODE, int OUTH>
__global__ void __launch_bounds__(256, 2) mmagemm_k(
    const __half* __restrict__ A,
    const __half* __restrict__ Wa, const __half* __restrict__ Wb, const __half* __restrict__ Wc,
    const float* __restrict__ ba, const float* __restrict__ bb, const float* __restrict__ bc,
    void* __restrict__ Cav, void* __restrict__ Cbv, void* __restrict__ Ccv,
    int N, int K)
{
    extern __shared__ char dynS[];

    const int tid  = threadIdx.x;
    const int lane = tid & 31;
    const int wid  = tid >> 5;
    const int g    = lane >> 2;
    const int tg   = lane & 3;
    const int wm   = wid & 1;       // m-half (64 rows)
    const int wn   = wid >> 1;      // n-quarter (32 cols)
    const int bm   = blockIdx.y * 128;

    const __half* W; const float* bias; void* Cv; int bn;
    if (MODE == 3) {
        int sel = blockIdx.x >> 1;
        W    = sel == 0 ? Wa : sel == 1 ? Wb : Wc;
        bias = sel == 0 ? ba : sel == 1 ? bb : bc;
        Cv   = sel == 0 ? Cav : sel == 1 ? Cbv : Ccv;
        bn = (blockIdx.x & 1) * 128;
    } else {
        W = Wa; bias = ba; Cv = Cav;
        bn = blockIdx.x * 128;
    }

    const uint32_t sBase = smem_u32(dynS);

    // ldmatrix per-lane base addresses (within a stage)
    const int lr = lane & 7;
    const int li = lane >> 3;
    const uint32_t aLd = sBase +
        (uint32_t)((wm * 64 + (li & 1) * 8 + lr) * ROWB + (li >> 1) * 16);
    const uint32_t bLd = sBase + ATILE_B +
        (uint32_t)((wn * 32 + lr) * ROWB + (li & 1) * 16);

    // staging: thread -> row tid>>1, half-row (tid&1)*32B; 2 chunks per matrix
    const int srow = tid >> 1;
    const int h16  = (tid & 1) * 16;   // halves offset within BK=32 row
    const uint32_t aSt = sBase + (uint32_t)(srow * ROWB + (tid & 1) * 32);
    const uint32_t bSt = aSt + (uint32_t)ATILE_B;

    const __half* Arow = A + (size_t)(bm + srow) * K;
    const __half* Brow = W + (size_t)(bn + srow) * K;

    const int nT = K >> 5;   // BK=32 halves

    // prologue: issue tiles 0..STAGES-2
    #pragma unroll
    for (int t = 0; t < STAGES - 1; t++) {
        uint32_t so = (uint32_t)(t * STAGE_B);
        const __half* as = Arow + t * 32 + h16;
        const __half* bs = Brow + t * 32 + h16;
        CP_ASYNC16(aSt + so,      as);
        CP_ASYNC16(aSt + so + 16, as + 8);
        CP_ASYNC16(bSt + so,      bs);
        CP_ASYNC16(bSt + so + 16, bs + 8);
        CP_COMMIT();
    }

    float acc[4][4][4] = {};
    int cs = 0, is = STAGES - 1;

    for (int t = 0; t < nT; t++) {
        CP_WAIT(STAGES - 2);
        __syncthreads();

        int ft = t + STAGES - 1;
        if (ft < nT) {
            uint32_t so = (uint32_t)(is * STAGE_B);
            const __half* as = Arow + ft * 32 + h16;
            const __half* bs = Brow + ft * 32 + h16;
            CP_ASYNC16(aSt + so,      as);
            CP_ASYNC16(aSt + so + 16, as + 8);
            CP_ASYNC16(bSt + so,      bs);
            CP_ASYNC16(bSt + so + 16, bs + 8);
        }
        CP_COMMIT();
        if (++is == STAGES) is = 0;

        // MMA on stage cs: 2 k-steps of 16
        const uint32_t so = (uint32_t)(cs * STAGE_B);
        #pragma unroll
        for (int ks = 0; ks < 2; ks++) {
            const uint32_t kOff = so + (uint32_t)(ks * 32);
            uint32_t af[4][4];
            #pragma unroll
            for (int mt = 0; mt < 4; mt++)
                LDSM_X4(af[mt][0], af[mt][1], af[mt][2], af[mt][3],
                        aLd + (uint32_t)(mt * 16 * ROWB) + kOff);
            uint32_t bf[4][2];
            #pragma unroll
            for (int nt = 0; nt < 4; nt++)
                LDSM_X2(bf[nt][0], bf[nt][1],
                        bLd + (uint32_t)(nt * 8 * ROWB) + kOff);
            #pragma unroll
            for (int mt = 0; mt < 4; mt++)
                #pragma unroll
                for (int nt = 0; nt < 4; nt++)
                    mma_f16(acc[mt][nt], af[mt], bf[nt]);
        }
        if (++cs == STAGES) cs = 0;
    }

    // epilogue: d0=(g,2tg) d1=(g,2tg+1) d2=(g+8,2tg) d3=(g+8,2tg+1)
    #pragma unroll
    for (int mt = 0; mt < 4; mt++) {
        int m0 = bm + wm * 64 + mt * 16 + g;
        int m1 = m0 + 8;
        bool k0 = true, k1 = true;
        if (MODE == 2) { k0 = g_use[m0] != 0; k1 = g_use[m1] != 0; }
        #pragma unroll
        for (int nt = 0; nt < 4; nt++) {
            int n = bn + wn * 32 + nt * 8 + 2 * tg;
            float2 bz = *reinterpret_cast<const float2*>(bias + n);
            float2 o0, o1;
            o0.x = acc[mt][nt][0] + bz.x; o0.y = acc[mt][nt][1] + bz.y;
            o1.x = acc[mt][nt][2] + bz.x; o1.y = acc[mt][nt][3] + bz.y;
            if (ACT == 1) {
                o0.x = gelu_f(o0.x); o0.y = gelu_f(o0.y);
                o1.x = gelu_f(o1.x); o1.y = gelu_f(o1.y);
            }
            if (MODE == 2) {
                if (!k0) o0 = *reinterpret_cast<const float2*>(&g_red[(size_t)m0 * 256 + n]);
                if (!k1) o1 = *reinterpret_cast<const float2*>(&g_red[(size_t)m1 * 256 + n]);
            }
            if (OUTH) {
                __half* Ch = (__half*)Cv;
                __half2 h0 = __floats2half2_rn(o0.x, o0.y);
                __half2 h1 = __floats2half2_rn(o1.x, o1.y);
                *reinterpret_cast<__half2*>(&Ch[(size_t)m0 * N + n]) = h0;
                *reinterpret_cast<__half2*>(&Ch[(size_t)m1 * N + n]) = h1;
            } else {
                float* C = (float*)Cv;
                *reinterpret_cast<float2*>(&C[(size_t)m0 * N + n]) = o0;
                *reinterpret_cast<float2*>(&C[(size_t)m1 * N + n]) = o1;
            }
        }
    }
}

// ---------------- LayerNorm over 256: one WARP per row, fp32+fp16 store ----------------
__global__ void ln_k(const float* __restrict__ gam, const float* __restrict__ bet)
{
    const int wid = threadIdx.x >> 5, lane = threadIdx.x & 31;
    const int r = blockIdx.x * 8 + wid;
    const float* x = &g_h2[(size_t)r * 256 + lane * 8];
    float4 v0 = *reinterpret_cast<const float4*>(x);
    float4 v1 = *reinterpret_cast<const float4*>(x + 4);
    float s = v0.x+v0.y+v0.z+v0.w + v1.x+v1.y+v1.z+v1.w;
    #pragma unroll
    for (int o = 16; o > 0; o >>= 1) s += __shfl_xor_sync(0xffffffffu, s, o);
    float mu = s * (1.0f / 256.0f);
    float d0x=v0.x-mu, d0y=v0.y-mu, d0z=v0.z-mu, d0w=v0.w-mu;
    float d1x=v1.x-mu, d1y=v1.y-mu, d1z=v1.z-mu, d1w=v1.w-mu;
    float sq = d0x*d0x+d0y*d0y+d0z*d0z+d0w*d0w + d1x*d1x+d1y*d1y+d1z*d1z+d1w*d1w;
    #pragma unroll
    for (int o = 16; o > 0; o >>= 1) sq += __shfl_xor_sync(0xffffffffu, sq, o);
    float rs = rsqrtf(sq * (1.0f / 256.0f) + 1e-5f);
    float4 ga0 = *reinterpret_cast<const float4*>(gam + lane * 8);
    float4 ga1 = *reinterpret_cast<const float4*>(gam + lane * 8 + 4);
    float4 be0 = *reinterpret_cast<const float4*>(bet + lane * 8);
    float4 be1 = *reinterpret_cast<const float4*>(bet + lane * 8 + 4);
    float4 o0, o1;
    o0.x = d0x*rs*ga0.x + be0.x; o0.y = d0y*rs*ga0.y + be0.y;
    o0.z = d0z*rs*ga0.z + be0.z; o0.w = d0w*rs*ga0.w + be0.w;
    o1.x = d1x*rs*ga1.x + be1.x; o1.y = d1y*rs*ga1.y + be1.y;
    o1.z = d1z*rs*ga1.z + be1.z; o1.w = d1w*rs*ga1.w + be1.w;
    float* y = &g_red[(size_t)r * 256 + lane * 8];
    *reinterpret_cast<float4*>(y)     = o0;
    *reinterpret_cast<float4*>(y + 4) = o1;
    // fp16 copy (QKV A input)
    __half2 h0 = __floats2half2_rn(o0.x, o0.y);
    __half2 h1 = __floats2half2_rn(o0.z, o0.w);
    __half2 h2 = __floats2half2_rn(o1.x, o1.y);
    __half2 h3 = __floats2half2_rn(o1.z, o1.w);
    uint4 hv;
    hv.x = *reinterpret_cast<uint32_t*>(&h0);
    hv.y = *reinterpret_cast<uint32_t*>(&h1);
    hv.z = *reinterpret_cast<uint32_t*>(&h2);
    hv.w = *reinterpret_cast<uint32_t*>(&h3);
    *reinterpret_cast<uint4*>(&g_redh[(size_t)r * 256 + lane * 8]) = hv;
}

// ---------------- attention: one block per batch, warp per head ----------------
__global__ void attn_k(const int* __restrict__ mask)
{
    int b = blockIdx.x, tid = threadIdx.x;
    int h = tid >> 5, lane = tid & 31;
    __shared__ float qs[Hsz][Ssz][33], ks[Hsz][Ssz][33], vs[Hsz][Ssz][33];
    __shared__ float sc[Hsz][Ssz][Ssz + 1];
    __shared__ int exS[Ssz];
    __shared__ int anyS;

    if (b == 0 && tid == 0) g_acc = 0.0f;
    if (tid < Ssz) exS[tid] = (mask[b * Ssz + tid] > 0);
    __syncthreads();
    if (tid == 0) { int a = 0; for (int s = 0; s < Ssz; s++) a |= exS[s]; anyS = a; }
    __syncthreads();
    if (tid < Ssz) g_use[b * Ssz + tid] = (unsigned char)((!exS[tid]) && anyS);

    #pragma unroll
    for (int s = 0; s < Ssz; s++) {
        size_t base = ((size_t)(b * Ssz + s)) * REDsz + h * DHsz + lane;
        qs[h][s][lane] = g_q[base];
        ks[h][s][lane] = g_k[base];
        vs[h][s][lane] = g_v[base];
    }
    __syncwarp();

    for (int idx = lane; idx < Ssz * Ssz; idx += 32) {
        int i = idx / Ssz, j = idx - i * Ssz;
        float dot = 0.0f;
        #pragma unroll
        for (int d = 0; d < 32; d++) dot += qs[h][i][d] * ks[h][j][d];
        sc[h][i][j] = exS[j] ? dot * 0.17677669529663687f : -1e9f;
    }
    __syncwarp();

    if (lane < Ssz) {
        int i = lane;
        float m = -1e30f;
        #pragma unroll
        for (int j = 0; j < Ssz; j++) m = fmaxf(m, sc[h][i][j]);
        float sum = 0.0f;
        #pragma unroll
        for (int j = 0; j < Ssz; j++) { float e = expf(sc[h][i][j] - m); sc[h][i][j] = e; sum += e; }
        float inv = 1.0f / sum;
        #pragma unroll
        for (int j = 0; j < Ssz; j++) sc[h][i][j] *= inv;
    }
    __syncwarp();

    #pragma unroll
    for (int i = 0; i < Ssz; i++) {
        float s = 0.0f;
        #pragma unroll
        for (int j = 0; j < Ssz; j++) s += sc[h][i][j] * vs[h][j][lane];
        g_ctxh[((size_t)(b * Ssz + i)) * REDsz + h * DHsz + lane] = __float2half_rn(s);
    }
}

// ---------------- merged orthogonality loss + logits: one block per batch ----------------
__global__ void losslogit_k(const float* __restrict__ Wp, const float* __restrict__ bp,
                            float* __restrict__ out, int loff)
{
    int b = blockIdx.x, tid = threadIdx.x;
    __shared__ float X[Ssz][REDsz + 1];
    __shared__ float inv[Ssz];
    __shared__ float mean[REDsz];
    for (int idx = tid; idx < Ssz * REDsz; idx += 256)
        X[idx >> 8][idx & 255] = g_upd[(size_t)b * Ssz * REDsz + idx];
    __syncthreads();
    int w = tid >> 5, lane = tid & 31;
    for (int r = w; r < Ssz; r += 8) {
        float s = 0.0f;
        for (int d = lane; d < 256; d += 32) s += X[r][d] * X[r][d];
        for (int o = 16; o > 0; o >>= 1) s += __shfl_down_sync(0xffffffffu, s, o);
        if (lane == 0) inv[r] = 1.0f / fmaxf(sqrtf(s), 1e-8f);
    }
    {
        float s = 0.0f;
        #pragma unroll
        for (int ss = 0; ss < Ssz; ss++) s += X[ss][tid];
        mean[tid] = s * (1.0f / (float)Ssz);
    }
    __syncthreads();
    float part = 0.0f;
    if (tid < (Ssz * (Ssz - 1)) / 2) {
        int p = tid, i = 0;
        while (p >= Ssz - 1 - i) { p -= Ssz - 1 - i; i++; }
        int j = i + 1 + p;
        float dot = 0.0f;
        for (int d = 0; d < 256; d++) dot += X[i][d] * X[j][d];
        float gv = fabsf(dot * inv[i] * inv[j]);
        part = fmaxf(gv - 0.1f, 0.0f) * 2.0f;
    }
    __shared__ float red[256];
    red[tid] = part; __syncthreads();
    for (int s = 128; s > 0; s >>= 1) { if (tid < s) red[tid] += red[tid + s]; __syncthreads(); }
    if (tid == 0) atomicAdd(&g_acc, red[0]);
    if (tid < NLAB) {
        float a = bp[tid];
        const float* wr = Wp + tid * REDsz;
        for (int d = 0; d < REDsz; d++) a += mean[d] * wr[d];
        out[loff + b * NLAB + tid] = a;
    }
}

__global__ void fin_k(float* out, int writeloss)
{
    if (writeloss)
        out[0] = g_acc * (1.0f / ((float)Bsz * Ssz * (Ssz - 1)));
}

// ---------------- launch ----------------
extern "C" void kernel_launch(void* const* d_in, const int* in_sizes, int n_in,
                              void* d_out, int out_size)
{
    const float* cls  = (const float*)d_in[0];
    const int*   mask = (const int*)  d_in[1];
    const float* miss = (const float*)d_in[2];
    const float* W1 = (const float*)d_in[3];  const float* b1 = (const float*)d_in[4];
    const float* W2 = (const float*)d_in[5];  const float* b2 = (const float*)d_in[6];
    const float* lg = (const float*)d_in[7];  const float* lb = (const float*)d_in[8];
    const float* Wq = (const float*)d_in[9];  const float* bq = (const float*)d_in[10];
    const float* Wk = (const float*)d_in[11]; const float* bk = (const float*)d_in[12];
    const float* Wv = (const float*)d_in[13]; const float* bv = (const float*)d_in[14];
    const float* Wo = (const float*)d_in[15]; const float* bo = (const float*)d_in[16];
    const float* Wp = (const float*)d_in[17]; const float* bp = (const float*)d_in[18];
    float* out = (float*)d_out;

    int loff = out_size - Bsz * NLAB;
    if (loff < 0) loff = 0;

    __half *ah, *h1h, *redh, *ctxh, *wh;
    float *h2, *red, *q, *k, *v, *upd;
    cudaGetSymbolAddress((void**)&ah,   g_ah);
    cudaGetSymbolAddress((void**)&h1h,  g_h1h);
    cudaGetSymbolAddress((void**)&h2,   g_h2);
    cudaGetSymbolAddress((void**)&red,  g_red);
    cudaGetSymbolAddress((void**)&redh, g_redh);
    cudaGetSymbolAddress((void**)&q,    g_q);
    cudaGetSymbolAddress((void**)&k,    g_k);
    cudaGetSymbolAddress((void**)&v,    g_v);
    cudaGetSymbolAddress((void**)&ctxh, g_ctxh);
    cudaGetSymbolAddress((void**)&upd,  g_upd);
    cudaGetSymbolAddress((void**)&wh,   g_wh);

    cudaFuncSetAttribute(mmagemm_k<1,0,1>, cudaFuncAttributeMaxDynamicSharedMemorySize, SMEM_DYN);
    cudaFuncSetAttribute(mmagemm_k<1,0,0>, cudaFuncAttributeMaxDynamicSharedMemorySize, SMEM_DYN);
    cudaFuncSetAttribute(mmagemm_k<0,3,0>, cudaFuncAttributeMaxDynamicSharedMemorySize, SMEM_DYN);
    cudaFuncSetAttribute(mmagemm_k<0,2,0>, cudaFuncAttributeMaxDynamicSharedMemorySize, SMEM_DYN);

    dim3 blk(256);
    // 0) prep: gather+fp16 A, fp16 weights
    gprep_k<<<(Mrows * (Esz / 4) + 255) / 256, 256>>>(cls, miss, mask);
    wprep_k<<<(WTOT + 255) / 256, 256>>>(W1, W2, Wq, Wk, Wv, Wo);
    // 1) GEMM1 + GELU -> fp16 h1 : [M,768] -> [M,384]
    mmagemm_k<1,0,1><<<dim3(3, Mrows/128), blk, SMEM_DYN>>>(
        ah, wh + OFF_W1, nullptr, nullptr, b1, nullptr, nullptr,
        h1h, nullptr, nullptr, 384, 768);
    // 2) GEMM2 + GELU : [M,384] -> [M,256] fp32
    mmagemm_k<1,0,0><<<dim3(2, Mrows/128), blk, SMEM_DYN>>>(
        h1h, wh + OFF_W2, nullptr, nullptr, b2, nullptr, nullptr,
        h2, nullptr, nullptr, 256, 384);
    // 3) LayerNorm -> g_red (fp32) + g_redh (fp16)
    ln_k<<<Mrows/8, 256>>>(lg, lb);
    // 4) fused QKV projections
    mmagemm_k<0,3,0><<<dim3(6, Mrows/128), blk, SMEM_DYN>>>(
        redh, wh + OFF_WQ, wh + OFF_WK, wh + OFF_WV, bq, bk, bv,
        q, k, v, 256, 256);
    // 5) attention (writes fp16 ctx, computes g_use, zeroes g_acc)
    attn_k<<<Bsz, 256>>>(mask);
    // 6) Wo projection + scatter-select epilogue -> g_upd
    mmagemm_k<0,2,0><<<dim3(2, Mrows/128), blk, SMEM_DYN>>>(
        ctxh, wh + OFF_WO, nullptr, nullptr, bo, nullptr, nullptr,
        upd, nullptr, nullptr, 256, 256);
    // 7) merged orthogonality loss + logits
    losslogit_k<<<Bsz, 256>>>(Wp, bp, out, loff);
    // 8) finalize loss scalar
    fin_k<<<1, 1>>>(out, loff >= 1 ? 1 : 0);
}

// round 13
// speedup vs baseline: 4.0466x; 1.2480x over previous
#include <cuda_runtime.h>
#include <cuda_fp16.h>
#include <math.h>
#include <stdint.h>

#define Bsz   2048
#define Ssz   23
#define Esz   768
#define REDsz 256
#define Hsz   8
#define DHsz  32
#define NLAB  25
#define Mrows (Bsz*Ssz)     // 47104
#define MCtiles 369         // ceil((Mrows+23)/128)
#define MCc   (MCtiles*128) // 47232 compacted capacity

// GEMM pipeline config: fp16, BK=32, 5 stages
#define STAGES    5
#define ROWB      80
#define ATILE_B   (128*ROWB)
#define STAGE_B   (2*ATILE_B)
#define SMEM_DYN  (STAGES*STAGE_B)

// fp16 weight scratch offsets (halves)
#define W1N  (384*768)
#define W2N  (256*384)
#define WQN  (256*256)
#define OFF_W1 0
#define OFF_W2 (OFF_W1 + W1N)
#define OFF_WQ (OFF_W2 + W2N)
#define OFF_WK (OFF_WQ + WQN)
#define OFF_WV (OFF_WK + WQN)
#define OFF_WO (OFF_WV + WQN)
#define WTOT   (OFF_WO + WQN)

// ---------------- scratch (allocation-free; zero-initialized) ----------------
__device__ __half g_ac  [(size_t)MCc*768];   // compacted GEMM1 A (fp16)
__device__ __half g_h1c [(size_t)MCc*384];   // compacted GEMM1 out
__device__ float  g_h2c [(size_t)MCc*256];   // compacted GEMM2 out
__device__ float  g_redc[(size_t)MCc*256];   // compacted LN out fp32
__device__ __half g_redch[(size_t)MCc*256];  // compacted LN out fp16
__device__ float  g_qc  [(size_t)MCc*256];
__device__ float  g_kc  [(size_t)MCc*256];
__device__ float  g_vc  [(size_t)MCc*256];
__device__ __half g_ctxh[(size_t)Mrows*256]; // full-M attention ctx (fp16)
__device__ float  g_upd [(size_t)Mrows*256];
__device__ __half g_wh  [WTOT];
__device__ int    g_r2c [Mrows];
__device__ int    g_cnt;
__device__ unsigned char g_use[Mrows];
__device__ float  g_acc;

__device__ __forceinline__ float gelu_f(float x) {
    return 0.5f * x * (1.0f + erff(x * 0.70710678118654752440f));
}

__device__ __forceinline__ uint32_t smem_u32(const void* p) {
    uint32_t a;
    asm("{ .reg .u64 t; cvta.to.shared.u64 t, %1; cvt.u32.u64 %0, t; }" : "=r"(a) : "l"(p));
    return a;
}

__device__ __forceinline__ void mma_f16(float* d, const uint32_t* a, const uint32_t* b) {
    asm volatile(
        "mma.sync.aligned.m16n8k16.row.col.f32.f16.f16.f32 "
        "{%0,%1,%2,%3}, {%4,%5,%6,%7}, {%8,%9}, {%0,%1,%2,%3};"
        : "+f"(d[0]), "+f"(d[1]), "+f"(d[2]), "+f"(d[3])
        : "r"(a[0]), "r"(a[1]), "r"(a[2]), "r"(a[3]), "r"(b[0]), "r"(b[1]));
}

#define LDSM_X4(r0_, r1_, r2_, r3_, addr_) \
    asm volatile("ldmatrix.sync.aligned.m8n8.x4.shared.b16 {%0,%1,%2,%3}, [%4];" \
                 : "=r"(r0_), "=r"(r1_), "=r"(r2_), "=r"(r3_) : "r"(addr_))
#define LDSM_X2(r0_, r1_, addr_) \
    asm volatile("ldmatrix.sync.aligned.m8n8.x2.shared.b16 {%0,%1}, [%2];" \
                 : "=r"(r0_), "=r"(r1_) : "r"(addr_))

#define CP_ASYNC16(dst_, src_) \
    asm volatile("cp.async.cg.shared.global [%0], [%1], 16;" :: "r"(dst_), "l"(src_) : "memory")
#define CP_COMMIT() asm volatile("cp.async.commit_group;" ::: "memory")
#define CP_WAIT(n_)  asm volatile("cp.async.wait_group %0;" :: "n"(n_) : "memory")

// ---------------- compaction prep ----------------
__global__ void zero_k() { g_cnt = 23; }

__global__ void assign_k(const int* __restrict__ mask)
{
    int r = blockIdx.x * 256 + threadIdx.x;
    if (r >= Mrows) return;
    if (mask[r] > 0) g_r2c[r] = atomicAdd(&g_cnt, 1);
    else             g_r2c[r] = r % Ssz;
}

// copy miss rows (23) + existing cls rows into compacted fp16 A
__global__ void acopy_k(const float* __restrict__ cls, const float* __restrict__ miss,
                        const int* __restrict__ mask)
{
    int idx = blockIdx.x * 256 + threadIdx.x;       // one 8-float chunk
    const int CH = Esz / 8;                         // 96 chunks per row
    if (idx >= (Mrows + Ssz) * CH) return;
    const float* src; int drow, c;
    if (idx < Ssz * CH) {
        int s = idx / CH; c = (idx - s * CH) * 8;
        src = miss + (size_t)s * Esz + c; drow = s;
    } else {
        int j = idx - Ssz * CH;
        int r = j / CH; c = (j - r * CH) * 8;
        if (mask[r] <= 0) return;
        src = cls + (size_t)r * Esz + c; drow = g_r2c[r];
    }
    float4 v0 = *reinterpret_cast<const float4*>(src);
    float4 v1 = *reinterpret_cast<const float4*>(src + 4);
    __half2 h0 = __floats2half2_rn(v0.x, v0.y);
    __half2 h1 = __floats2half2_rn(v0.z, v0.w);
    __half2 h2 = __floats2half2_rn(v1.x, v1.y);
    __half2 h3 = __floats2half2_rn(v1.z, v1.w);
    uint4 o;
    o.x = *reinterpret_cast<uint32_t*>(&h0);
    o.y = *reinterpret_cast<uint32_t*>(&h1);
    o.z = *reinterpret_cast<uint32_t*>(&h2);
    o.w = *reinterpret_cast<uint32_t*>(&h3);
    *reinterpret_cast<uint4*>(&g_ac[(size_t)drow * Esz + c]) = o;
}

__global__ void wprep_k(const float* __restrict__ W1, const float* __restrict__ W2,
                        const float* __restrict__ Wq, const float* __restrict__ Wk,
                        const float* __restrict__ Wv, const float* __restrict__ Wo)
{
    int i = blockIdx.x * 256 + threadIdx.x;
    if (i >= WTOT) return;
    float v;
    if      (i < OFF_W2) v = W1[i - OFF_W1];
    else if (i < OFF_WQ) v = W2[i - OFF_W2];
    else if (i < OFF_WK) v = Wq[i - OFF_WQ];
    else if (i < OFF_WV) v = Wk[i - OFF_WK];
    else if (i < OFF_WO) v = Wv[i - OFF_WV];
    else                 v = Wo[i - OFF_WO];
    g_wh[i] = __float2half_rn(v);
}

// ---------------- HMMA fp16 GEMM, cp.async 5-stage pipeline ----------------
// BM=BN=128, BK=32 halves, 256 threads, warp tile 64x32.
// GUARD: early-exit CTAs whose bm >= *g_cnt (compacted kernels).
// MODE 0: plain. MODE 2: select vs redc via r2c (N=256). MODE 3: fused QKV.
template<int ACT, int MODE, int OUTH, int GUARD>
__global__ void __launch_bounds__(256, 2) mmagemm_k(
    const __half* __restrict__ A,
    const __half* __restrict__ Wa, const __half* __restrict__ Wb, const __half* __restrict__ Wc,
    const float* __restrict__ ba, const float* __restrict__ bb, const float* __restrict__ bc,
    void* __restrict__ Cav, void* __restrict__ Cbv, void* __restrict__ Ccv,
    int N, int K)
{
    extern __shared__ char dynS[];

    const int bm = blockIdx.y * 128;
    if (GUARD) { if (bm >= g_cnt) return; }

    const int tid  = threadIdx.x;
    const int lane = tid & 31;
    const int wid  = tid >> 5;
    const int g    = lane >> 2;
    const int tg   = lane & 3;
    const int wm   = wid & 1;
    const int wn   = wid >> 1;

    const __half* W; const float* bias; void* Cv; int bn;
    if (MODE == 3) {
        int sel = blockIdx.x >> 1;
        W    = sel == 0 ? Wa : sel == 1 ? Wb : Wc;
        bias = sel == 0 ? ba : sel == 1 ? bb : bc;
        Cv   = sel == 0 ? Cav : sel == 1 ? Cbv : Ccv;
        bn = (blockIdx.x & 1) * 128;
    } else {
        W = Wa; bias = ba; Cv = Cav;
        bn = blockIdx.x * 128;
    }

    const uint32_t sBase = smem_u32(dynS);

    const int lr = lane & 7;
    const int li = lane >> 3;
    const uint32_t aLd = sBase +
        (uint32_t)((wm * 64 + (li & 1) * 8 + lr) * ROWB + (li >> 1) * 16);
    const uint32_t bLd = sBase + ATILE_B +
        (uint32_t)((wn * 32 + lr) * ROWB + (li & 1) * 16);

    const int srow = tid >> 1;
    const int h16  = (tid & 1) * 16;
    const uint32_t aSt = sBase + (uint32_t)(srow * ROWB + (tid & 1) * 32);
    const uint32_t bSt = aSt + (uint32_t)ATILE_B;

    const __half* Arow = A + (size_t)(bm + srow) * K;
    const __half* Brow = W + (size_t)(bn + srow) * K;

    const int nT = K >> 5;

    #pragma unroll
    for (int t = 0; t < STAGES - 1; t++) {
        uint32_t so = (uint32_t)(t * STAGE_B);
        const __half* as = Arow + t * 32 + h16;
        const __half* bs = Brow + t * 32 + h16;
        CP_ASYNC16(aSt + so,      as);
        CP_ASYNC16(aSt + so + 16, as + 8);
        CP_ASYNC16(bSt + so,      bs);
        CP_ASYNC16(bSt + so + 16, bs + 8);
        CP_COMMIT();
    }

    float acc[4][4][4] = {};
    int cs = 0, is = STAGES - 1;

    for (int t = 0; t < nT; t++) {
        CP_WAIT(STAGES - 2);
        __syncthreads();

        int ft = t + STAGES - 1;
        if (ft < nT) {
            uint32_t so = (uint32_t)(is * STAGE_B);
            const __half* as = Arow + ft * 32 + h16;
            const __half* bs = Brow + ft * 32 + h16;
            CP_ASYNC16(aSt + so,      as);
            CP_ASYNC16(aSt + so + 16, as + 8);
            CP_ASYNC16(bSt + so,      bs);
            CP_ASYNC16(bSt + so + 16, bs + 8);
        }
        CP_COMMIT();
        if (++is == STAGES) is = 0;

        const uint32_t so = (uint32_t)(cs * STAGE_B);
        #pragma unroll
        for (int ks = 0; ks < 2; ks++) {
            const uint32_t kOff = so + (uint32_t)(ks * 32);
            uint32_t af[4][4];
            #pragma unroll
            for (int mt = 0; mt < 4; mt++)
                LDSM_X4(af[mt][0], af[mt][1], af[mt][2], af[mt][3],
                        aLd + (uint32_t)(mt * 16 * ROWB) + kOff);
            uint32_t bf[4][2];
            #pragma unroll
            for (int nt = 0; nt < 4; nt++)
                LDSM_X2(bf[nt][0], bf[nt][1],
                        bLd + (uint32_t)(nt * 8 * ROWB) + kOff);
            #pragma unroll
            for (int mt = 0; mt < 4; mt++)
                #pragma unroll
                for (int nt = 0; nt < 4; nt++)
                    mma_f16(acc[mt][nt], af[mt], bf[nt]);
        }
        if (++cs == STAGES) cs = 0;
    }

    #pragma unroll
    for (int mt = 0; mt < 4; mt++) {
        int m0 = bm + wm * 64 + mt * 16 + g;
        int m1 = m0 + 8;
        bool k0 = true, k1 = true;
        int i0 = 0, i1 = 0;
        if (MODE == 2) {
            k0 = g_use[m0] != 0; k1 = g_use[m1] != 0;
            if (!k0) i0 = g_r2c[m0];
            if (!k1) i1 = g_r2c[m1];
        }
        #pragma unroll
        for (int nt = 0; nt < 4; nt++) {
            int n = bn + wn * 32 + nt * 8 + 2 * tg;
            float2 bz = *reinterpret_cast<const float2*>(bias + n);
            float2 o0, o1;
            o0.x = acc[mt][nt][0] + bz.x; o0.y = acc[mt][nt][1] + bz.y;
            o1.x = acc[mt][nt][2] + bz.x; o1.y = acc[mt][nt][3] + bz.y;
            if (ACT == 1) {
                o0.x = gelu_f(o0.x); o0.y = gelu_f(o0.y);
                o1.x = gelu_f(o1.x); o1.y = gelu_f(o1.y);
            }
            if (MODE == 2) {
                if (!k0) o0 = *reinterpret_cast<const float2*>(&g_redc[(size_t)i0 * 256 + n]);
                if (!k1) o1 = *reinterpret_cast<const float2*>(&g_redc[(size_t)i1 * 256 + n]);
            }
            if (OUTH) {
                __half* Ch = (__half*)Cv;
                __half2 h0 = __floats2half2_rn(o0.x, o0.y);
                __half2 h1 = __floats2half2_rn(o1.x, o1.y);
                *reinterpret_cast<__half2*>(&Ch[(size_t)m0 * N + n]) = h0;
                *reinterpret_cast<__half2*>(&Ch[(size_t)m1 * N + n]) = h1;
            } else {
                float* C = (float*)Cv;
                *reinterpret_cast<float2*>(&C[(size_t)m0 * N + n]) = o0;
                *reinterpret_cast<float2*>(&C[(size_t)m1 * N + n]) = o1;
            }
        }
    }
}

// ---------------- LayerNorm (compacted): one WARP per row ----------------
__global__ void ln_k(const float* __restrict__ gam, const float* __restrict__ bet)
{
    const int wid = threadIdx.x >> 5, lane = threadIdx.x & 31;
    const int r = blockIdx.x * 8 + wid;
    if (r >= g_cnt) return;
    const float* x = &g_h2c[(size_t)r * 256 + lane * 8];
    float4 v0 = *reinterpret_cast<const float4*>(x);
    float4 v1 = *reinterpret_cast<const float4*>(x + 4);
    float s = v0.x+v0.y+v0.z+v0.w + v1.x+v1.y+v1.z+v1.w;
    #pragma unroll
    for (int o = 16; o > 0; o >>= 1) s += __shfl_xor_sync(0xffffffffu, s, o);
    float mu = s * (1.0f / 256.0f);
    float d0x=v0.x-mu, d0y=v0.y-mu, d0z=v0.z-mu, d0w=v0.w-mu;
    float d1x=v1.x-mu, d1y=v1.y-mu, d1z=v1.z-mu, d1w=v1.w-mu;
    float sq = d0x*d0x+d0y*d0y+d0z*d0z+d0w*d0w + d1x*d1x+d1y*d1y+d1z*d1z+d1w*d1w;
    #pragma unroll
    for (int o = 16; o > 0; o >>= 1) sq += __shfl_xor_sync(0xffffffffu, sq, o);
    float rs = rsqrtf(sq * (1.0f / 256.0f) + 1e-5f);
    float4 ga0 = *reinterpret_cast<const float4*>(gam + lane * 8);
    float4 ga1 = *reinterpret_cast<const float4*>(gam + lane * 8 + 4);
    float4 be0 = *reinterpret_cast<const float4*>(bet + lane * 8);
    float4 be1 = *reinterpret_cast<const float4*>(bet + lane * 8 + 4);
    float4 o0, o1;
    o0.x = d0x*rs*ga0.x + be0.x; o0.y = d0y*rs*ga0.y + be0.y;
    o0.z = d0z*rs*ga0.z + be0.z; o0.w = d0w*rs*ga0.w + be0.w;
    o1.x = d1x*rs*ga1.x + be1.x; o1.y = d1y*rs*ga1.y + be1.y;
    o1.z = d1z*rs*ga1.z + be1.z; o1.w = d1w*rs*ga1.w + be1.w;
    float* y = &g_redc[(size_t)r * 256 + lane * 8];
    *reinterpret_cast<float4*>(y)     = o0;
    *reinterpret_cast<float4*>(y + 4) = o1;
    __half2 h0 = __floats2half2_rn(o0.x, o0.y);
    __half2 h1 = __floats2half2_rn(o0.z, o0.w);
    __half2 h2 = __floats2half2_rn(o1.x, o1.y);
    __half2 h3 = __floats2half2_rn(o1.z, o1.w);
    uint4 hv;
    hv.x = *reinterpret_cast<uint32_t*>(&h0);
    hv.y = *reinterpret_cast<uint32_t*>(&h1);
    hv.z = *reinterpret_cast<uint32_t*>(&h2);
    hv.w = *reinterpret_cast<uint32_t*>(&h3);
    *reinterpret_cast<uint4*>(&g_redch[(size_t)r * 256 + lane * 8]) = hv;
}

// ---------------- attention: block per batch, warp per head, q/k/v via r2c ----------------
__global__ void attn_k(const int* __restrict__ mask)
{
    int b = blockIdx.x, tid = threadIdx.x;
    int h = tid >> 5, lane = tid & 31;
    __shared__ float qs[Hsz][Ssz][33], ks[Hsz][Ssz][33], vs[Hsz][Ssz][33];
    __shared__ float sc[Hsz][Ssz][Ssz + 1];
    __shared__ int exS[Ssz];
    __shared__ int idxS[Ssz];
    __shared__ int anyS;

    if (b == 0 && tid == 0) g_acc = 0.0f;
    if (tid < Ssz) {
        exS[tid]  = (mask[b * Ssz + tid] > 0);
        idxS[tid] = g_r2c[b * Ssz + tid];
    }
    __syncthreads();
    if (tid == 0) { int a = 0; for (int s = 0; s < Ssz; s++) a |= exS[s]; anyS = a; }
    __syncthreads();
    if (tid < Ssz) g_use[b * Ssz + tid] = (unsigned char)((!exS[tid]) && anyS);

    #pragma unroll
    for (int s = 0; s < Ssz; s++) {
        size_t base = (size_t)idxS[s] * REDsz + h * DHsz + lane;
        qs[h][s][lane] = g_qc[base];
        ks[h][s][lane] = g_kc[base];
        vs[h][s][lane] = g_vc[base];
    }
    __syncwarp();

    for (int idx = lane; idx < Ssz * Ssz; idx += 32) {
        int i = idx / Ssz, j = idx - i * Ssz;
        float dot = 0.0f;
        #pragma unroll
        for (int d = 0; d < 32; d++) dot += qs[h][i][d] * ks[h][j][d];
        sc[h][i][j] = exS[j] ? dot * 0.17677669529663687f : -1e9f;
    }
    __syncwarp();

    if (lane < Ssz) {
        int i = lane;
        float m = -1e30f;
        #pragma unroll
        for (int j = 0; j < Ssz; j++) m = fmaxf(m, sc[h][i][j]);
        float sum = 0.0f;
        #pragma unroll
        for (int j = 0; j < Ssz; j++) { float e = expf(sc[h][i][j] - m); sc[h][i][j] = e; sum += e; }
        float inv = 1.0f / sum;
        #pragma unroll
        for (int j = 0; j < Ssz; j++) sc[h][i][j] *= inv;
    }
    __syncwarp();

    #pragma unroll
    for (int i = 0; i < Ssz; i++) {
        float s = 0.0f;
        #pragma unroll
        for (int j = 0; j < Ssz; j++) s += sc[h][i][j] * vs[h][j][lane];
        g_ctxh[((size_t)(b * Ssz + i)) * REDsz + h * DHsz + lane] = __float2half_rn(s);
    }
}

// ---------------- merged orthogonality loss + logits ----------------
__global__ void losslogit_k(const float* __restrict__ Wp, const float* __restrict__ bp,
                            float* __restrict__ out, int loff)
{
    int b = blockIdx.x, tid = threadIdx.x;
    __shared__ float X[Ssz][REDsz + 1];
    __shared__ float inv[Ssz];
    __shared__ float mean[REDsz];
    for (int idx = tid; idx < Ssz * REDsz; idx += 256)
        X[idx >> 8][idx & 255] = g_upd[(size_t)b * Ssz * REDsz + idx];
    __syncthreads();
    int w = tid >> 5, lane = tid & 31;
    for (int r = w; r < Ssz; r += 8) {
        float s = 0.0f;
        for (int d = lane; d < 256; d += 32) s += X[r][d] * X[r][d];
        for (int o = 16; o > 0; o >>= 1) s += __shfl_down_sync(0xffffffffu, s, o);
        if (lane == 0) inv[r] = 1.0f / fmaxf(sqrtf(s), 1e-8f);
    }
    {
        float s = 0.0f;
        #pragma unroll
        for (int ss = 0; ss < Ssz; ss++) s += X[ss][tid];
        mean[tid] = s * (1.0f / (float)Ssz);
    }
    __syncthreads();
    float part = 0.0f;
    if (tid < (Ssz * (Ssz - 1)) / 2) {
        int p = tid, i = 0;
        while (p >= Ssz - 1 - i) { p -= Ssz - 1 - i; i++; }
        int j = i + 1 + p;
        float dot = 0.0f;
        for (int d = 0; d < 256; d++) dot += X[i][d] * X[j][d];
        float gv = fabsf(dot * inv[i] * inv[j]);
        part = fmaxf(gv - 0.1f, 0.0f) * 2.0f;
    }
    __shared__ float red[256];
    red[tid] = part; __syncthreads();
    for (int s = 128; s > 0; s >>= 1) { if (tid < s) red[tid] += red[tid + s]; __syncthreads(); }
    if (tid == 0) atomicAdd(&g_acc, red[0]);
    if (tid < NLAB) {
        float a = bp[tid];
        const float* wr = Wp + tid * REDsz;
        for (int d = 0; d < REDsz; d++) a += mean[d] * wr[d];
        out[loff + b * NLAB + tid] = a;
    }
}

__global__ void fin_k(float* out, int writeloss)
{
    if (writeloss)
        out[0] = g_acc * (1.0f / ((float)Bsz * Ssz * (Ssz - 1)));
}

// ---------------- launch ----------------
extern "C" void kernel_launch(void* const* d_in, const int* in_sizes, int n_in,
                              void* d_out, int out_size)
{
    const float* cls  = (const float*)d_in[0];
    const int*   mask = (const int*)  d_in[1];
    const float* miss = (const float*)d_in[2];
    const float* W1 = (const float*)d_in[3];  const float* b1 = (const float*)d_in[4];
    const float* W2 = (const float*)d_in[5];  const float* b2 = (const float*)d_in[6];
    const float* lg = (const float*)d_in[7];  const float* lb = (const float*)d_in[8];
    const float* Wq = (const float*)d_in[9];  const float* bq = (const float*)d_in[10];
    const float* Wk = (const float*)d_in[11]; const float* bk = (const float*)d_in[12];
    const float* Wv = (const float*)d_in[13]; const float* bv = (const float*)d_in[14];
    const float* Wo = (const float*)d_in[15]; const float* bo = (const float*)d_in[16];
    const float* Wp = (const float*)d_in[17]; const float* bp = (const float*)d_in[18];
    float* out = (float*)d_out;

    int loff = out_size - Bsz * NLAB;
    if (loff < 0) loff = 0;

    __half *ac, *h1c, *redch, *ctxh, *wh;
    float *h2c, *qc, *kc, *vc, *upd;
    cudaGetSymbolAddress((void**)&ac,    g_ac);
    cudaGetSymbolAddress((void**)&h1c,   g_h1c);
    cudaGetSymbolAddress((void**)&h2c,   g_h2c);
    cudaGetSymbolAddress((void**)&redch, g_redch);
    cudaGetSymbolAddress((void**)&qc,    g_qc);
    cudaGetSymbolAddress((void**)&kc,    g_kc);
    cudaGetSymbolAddress((void**)&vc,    g_vc);
    cudaGetSymbolAddress((void**)&ctxh,  g_ctxh);
    cudaGetSymbolAddress((void**)&upd,   g_upd);
    cudaGetSymbolAddress((void**)&wh,    g_wh);

    cudaFuncSetAttribute(mmagemm_k<1,0,1,1>, cudaFuncAttributeMaxDynamicSharedMemorySize, SMEM_DYN);
    cudaFuncSetAttribute(mmagemm_k<1,0,0,1>, cudaFuncAttributeMaxDynamicSharedMemorySize, SMEM_DYN);
    cudaFuncSetAttribute(mmagemm_k<0,3,0,1>, cudaFuncAttributeMaxDynamicSharedMemorySize, SMEM_DYN);
    cudaFuncSetAttribute(mmagemm_k<0,2,0,0>, cudaFuncAttributeMaxDynamicSharedMemorySize, SMEM_DYN);

    dim3 blk(256);
    // 0) compaction + weight prep
    zero_k<<<1, 1>>>();
    assign_k<<<(Mrows + 255) / 256, 256>>>(mask);
    acopy_k<<<(((Mrows + Ssz) * (Esz / 8)) + 255) / 256, 256>>>(cls, miss, mask);
    wprep_k<<<(WTOT + 255) / 256, 256>>>(W1, W2, Wq, Wk, Wv, Wo);
    // 1) GEMM1 + GELU (compacted) -> fp16 h1c
    mmagemm_k<1,0,1,1><<<dim3(3, MCtiles), blk, SMEM_DYN>>>(
        ac, wh + OFF_W1, nullptr, nullptr, b1, nullptr, nullptr,
        h1c, nullptr, nullptr, 384, 768);
    // 2) GEMM2 + GELU (compacted) -> fp32 h2c
    mmagemm_k<1,0,0,1><<<dim3(2, MCtiles), blk, SMEM_DYN>>>(
        h1c, wh + OFF_W2, nullptr, nullptr, b2, nullptr, nullptr,
        h2c, nullptr, nullptr, 256, 384);
    // 3) LayerNorm (compacted) -> redc + redch
    ln_k<<<MCc / 8, 256>>>(lg, lb);
    // 4) fused QKV (compacted)
    mmagemm_k<0,3,0,1><<<dim3(6, MCtiles), blk, SMEM_DYN>>>(
        redch, wh + OFF_WQ, wh + OFF_WK, wh + OFF_WV, bq, bk, bv,
        qc, kc, vc, 256, 256);
    // 5) attention (full M; q/k/v via r2c; computes g_use, zeroes g_acc)
    attn_k<<<Bsz, 256>>>(mask);
    // 6) Wo + scatter-select (full M) -> g_upd
    mmagemm_k<0,2,0,0><<<dim3(2, Mrows/128), blk, SMEM_DYN>>>(
        ctxh, wh + OFF_WO, nullptr, nullptr, bo, nullptr, nullptr,
        upd, nullptr, nullptr, 256, 256);
    // 7) merged orthogonality loss + logits
    losslogit_k<<<Bsz, 256>>>(Wp, bp, out, loff);
    // 8) finalize loss scalar
    fin_k<<<1, 1>>>(out, loff >= 1 ? 1 : 0);
}

// round 14
// speedup vs baseline: 4.3236x; 1.0684x over previous
#include <cuda_runtime.h>
#include <cuda_fp16.h>
#include <math.h>
#include <stdint.h>

#define Bsz   2048
#define Ssz   23
#define Esz   768
#define REDsz 256
#define Hsz   8
#define DHsz  32
#define NLAB  25
#define Mrows (Bsz*Ssz)     // 47104
#define MCtiles 369
#define MCc   (MCtiles*128) // 47232

// GEMM pipeline config: fp16, BK=32, 5 stages
#define STAGES    5
#define ROWB      80
#define ATILE_B   (128*ROWB)
#define STAGE_B   (2*ATILE_B)
#define SMEM_DYN  (STAGES*STAGE_B)

// fp16 weight scratch offsets (halves)
#define W1N  (384*768)
#define W2N  (256*384)
#define WQN  (256*256)
#define OFF_W1 0
#define OFF_W2 (OFF_W1 + W1N)
#define OFF_WQ (OFF_W2 + W2N)
#define OFF_WK (OFF_WQ + WQN)
#define OFF_WV (OFF_WK + WQN)
#define OFF_WO (OFF_WV + WQN)
#define WTOT   (OFF_WO + WQN)

// ---------------- scratch (allocation-free; zero-initialized) ----------------
__device__ __half g_ac   [(size_t)MCc*768];
__device__ __half g_h1c  [(size_t)MCc*384];
__device__ float  g_h2c  [(size_t)MCc*256];
__device__ float  g_redc [(size_t)MCc*256];
__device__ __half g_redch[(size_t)MCc*256];
__device__ float  g_qc   [(size_t)MCc*256];
__device__ float  g_kc   [(size_t)MCc*256];
__device__ float  g_vc   [(size_t)MCc*256];
__device__ __half g_ctxc [(size_t)MCc*256];   // compacted missing-row ctx
__device__ float  g_updc [(size_t)MCc*256];   // compacted missing-row mha_out
__device__ __half g_wh   [WTOT];
__device__ int    g_r2c  [Mrows];
__device__ int    g_m2c  [Mrows];
__device__ int    g_any  [Bsz];
__device__ int    g_cnt;
__device__ int    g_mcnt;
__device__ unsigned char g_use[Mrows];
__device__ float  g_acc;

__device__ __forceinline__ float gelu_f(float x) {
    return 0.5f * x * (1.0f + erff(x * 0.70710678118654752440f));
}

__device__ __forceinline__ uint32_t smem_u32(const void* p) {
    uint32_t a;
    asm("{ .reg .u64 t; cvta.to.shared.u64 t, %1; cvt.u32.u64 %0, t; }" : "=r"(a) : "l"(p));
    return a;
}

__device__ __forceinline__ void mma_f16(float* d, const uint32_t* a, const uint32_t* b) {
    asm volatile(
        "mma.sync.aligned.m16n8k16.row.col.f32.f16.f16.f32 "
        "{%0,%1,%2,%3}, {%4,%5,%6,%7}, {%8,%9}, {%0,%1,%2,%3};"
        : "+f"(d[0]), "+f"(d[1]), "+f"(d[2]), "+f"(d[3])
        : "r"(a[0]), "r"(a[1]), "r"(a[2]), "r"(a[3]), "r"(b[0]), "r"(b[1]));
}

#define LDSM_X4(r0_, r1_, r2_, r3_, addr_) \
    asm volatile("ldmatrix.sync.aligned.m8n8.x4.shared.b16 {%0,%1,%2,%3}, [%4];" \
                 : "=r"(r0_), "=r"(r1_), "=r"(r2_), "=r"(r3_) : "r"(addr_))
#define LDSM_X2(r0_, r1_, addr_) \
    asm volatile("ldmatrix.sync.aligned.m8n8.x2.shared.b16 {%0,%1}, [%2];" \
                 : "=r"(r0_), "=r"(r1_) : "r"(addr_))

#define CP_ASYNC16(dst_, src_) \
    asm volatile("cp.async.cg.shared.global [%0], [%1], 16;" :: "r"(dst_), "l"(src_) : "memory")
#define CP_COMMIT() asm volatile("cp.async.commit_group;" ::: "memory")
#define CP_WAIT(n_)  asm volatile("cp.async.wait_group %0;" :: "n"(n_) : "memory")

// ---------------- prep: per-batch any_exist + counter init ----------------
__global__ void prep_k(const int* __restrict__ mask)
{
    int b = blockIdx.x * 256 + threadIdx.x;
    if (b == 0) { g_cnt = Ssz; g_mcnt = 0; }
    if (b >= Bsz) return;
    int a = 0;
    #pragma unroll
    for (int s = 0; s < Ssz; s++) a |= (mask[b * Ssz + s] > 0);
    g_any[b] = a;
}

__global__ void assign_k(const int* __restrict__ mask)
{
    int r = blockIdx.x * 256 + threadIdx.x;
    if (r >= Mrows) return;
    int exist = mask[r] > 0;
    if (exist) g_r2c[r] = atomicAdd(&g_cnt, 1);
    else       g_r2c[r] = r % Ssz;
    int use = (!exist) && g_any[r / Ssz];
    g_use[r] = (unsigned char)use;
    if (use) g_m2c[r] = atomicAdd(&g_mcnt, 1);
}

// copy miss rows (23) + existing cls rows into compacted fp16 A
__global__ void acopy_k(const float* __restrict__ cls, const float* __restrict__ miss,
                        const int* __restrict__ mask)
{
    int idx = blockIdx.x * 256 + threadIdx.x;
    const int CH = Esz / 8;
    if (idx >= (Mrows + Ssz) * CH) return;
    const float* src; int drow, c;
    if (idx < Ssz * CH) {
        int s = idx / CH; c = (idx - s * CH) * 8;
        src = miss + (size_t)s * Esz + c; drow = s;
    } else {
        int j = idx - Ssz * CH;
        int r = j / CH; c = (j - r * CH) * 8;
        if (mask[r] <= 0) return;
        src = cls + (size_t)r * Esz + c; drow = g_r2c[r];
    }
    float4 v0 = *reinterpret_cast<const float4*>(src);
    float4 v1 = *reinterpret_cast<const float4*>(src + 4);
    __half2 h0 = __floats2half2_rn(v0.x, v0.y);
    __half2 h1 = __floats2half2_rn(v0.z, v0.w);
    __half2 h2 = __floats2half2_rn(v1.x, v1.y);
    __half2 h3 = __floats2half2_rn(v1.z, v1.w);
    uint4 o;
    o.x = *reinterpret_cast<uint32_t*>(&h0);
    o.y = *reinterpret_cast<uint32_t*>(&h1);
    o.z = *reinterpret_cast<uint32_t*>(&h2);
    o.w = *reinterpret_cast<uint32_t*>(&h3);
    *reinterpret_cast<uint4*>(&g_ac[(size_t)drow * Esz + c]) = o;
}

__global__ void wprep_k(const float* __restrict__ W1, const float* __restrict__ W2,
                        const float* __restrict__ Wq, const float* __restrict__ Wk,
                        const float* __restrict__ Wv, const float* __restrict__ Wo)
{
    int i = blockIdx.x * 256 + threadIdx.x;
    if (i >= WTOT) return;
    float v;
    if      (i < OFF_W2) v = W1[i - OFF_W1];
    else if (i < OFF_WQ) v = W2[i - OFF_W2];
    else if (i < OFF_WK) v = Wq[i - OFF_WQ];
    else if (i < OFF_WV) v = Wk[i - OFF_WK];
    else if (i < OFF_WO) v = Wv[i - OFF_WV];
    else                 v = Wo[i - OFF_WO];
    g_wh[i] = __float2half_rn(v);
}

// ---------------- HMMA fp16 GEMM, cp.async 5-stage pipeline ----------------
// GUARD: 0 none, 1 exit if bm>=g_cnt, 2 exit if bm>=g_mcnt.
// MODE 0: plain. MODE 3: fused QKV (grid.x=6; q-branch only tile bm==0).
template<int ACT, int MODE, int OUTH, int GUARD>
__global__ void __launch_bounds__(256, 2) mmagemm_k(
    const __half* __restrict__ A,
    const __half* __restrict__ Wa, const __half* __restrict__ Wb, const __half* __restrict__ Wc,
    const float* __restrict__ ba, const float* __restrict__ bb, const float* __restrict__ bc,
    void* __restrict__ Cav, void* __restrict__ Cbv, void* __restrict__ Ccv,
    int N, int K)
{
    extern __shared__ char dynS[];

    const int bm = blockIdx.y * 128;
    if (GUARD == 1) { if (bm >= g_cnt)  return; }
    if (GUARD == 2) { if (bm >= g_mcnt) return; }

    const int tid  = threadIdx.x;
    const int lane = tid & 31;
    const int wid  = tid >> 5;
    const int g    = lane >> 2;
    const int tg   = lane & 3;
    const int wm   = wid & 1;
    const int wn   = wid >> 1;

    const __half* W; const float* bias; void* Cv; int bn;
    if (MODE == 3) {
        int sel = blockIdx.x >> 1;
        if (sel == 0 && bm > 0) return;     // q needed only for miss rows 0..22
        W    = sel == 0 ? Wa : sel == 1 ? Wb : Wc;
        bias = sel == 0 ? ba : sel == 1 ? bb : bc;
        Cv   = sel == 0 ? Cav : sel == 1 ? Cbv : Ccv;
        bn = (blockIdx.x & 1) * 128;
    } else {
        W = Wa; bias = ba; Cv = Cav;
        bn = blockIdx.x * 128;
    }

    const uint32_t sBase = smem_u32(dynS);

    const int lr = lane & 7;
    const int li = lane >> 3;
    const uint32_t aLd = sBase +
        (uint32_t)((wm * 64 + (li & 1) * 8 + lr) * ROWB + (li >> 1) * 16);
    const uint32_t bLd = sBase + ATILE_B +
        (uint32_t)((wn * 32 + lr) * ROWB + (li & 1) * 16);

    const int srow = tid >> 1;
    const int h16  = (tid & 1) * 16;
    const uint32_t aSt = sBase + (uint32_t)(srow * ROWB + (tid & 1) * 32);
    const uint32_t bSt = aSt + (uint32_t)ATILE_B;

    const __half* Arow = A + (size_t)(bm + srow) * K;
    const __half* Brow = W + (size_t)(bn + srow) * K;

    const int nT = K >> 5;

    #pragma unroll
    for (int t = 0; t < STAGES - 1; t++) {
        uint32_t so = (uint32_t)(t * STAGE_B);
        const __half* as = Arow + t * 32 + h16;
        const __half* bs = Brow + t * 32 + h16;
        CP_ASYNC16(aSt + so,      as);
        CP_ASYNC16(aSt + so + 16, as + 8);
        CP_ASYNC16(bSt + so,      bs);
        CP_ASYNC16(bSt + so + 16, bs + 8);
        CP_COMMIT();
    }

    float acc[4][4][4] = {};
    int cs = 0, is = STAGES - 1;

    for (int t = 0; t < nT; t++) {
        CP_WAIT(STAGES - 2);
        __syncthreads();

        int ft = t + STAGES - 1;
        if (ft < nT) {
            uint32_t so = (uint32_t)(is * STAGE_B);
            const __half* as = Arow + ft * 32 + h16;
            const __half* bs = Brow + ft * 32 + h16;
            CP_ASYNC16(aSt + so,      as);
            CP_ASYNC16(aSt + so + 16, as + 8);
            CP_ASYNC16(bSt + so,      bs);
            CP_ASYNC16(bSt + so + 16, bs + 8);
        }
        CP_COMMIT();
        if (++is == STAGES) is = 0;

        const uint32_t so = (uint32_t)(cs * STAGE_B);
        #pragma unroll
        for (int ks = 0; ks < 2; ks++) {
            const uint32_t kOff = so + (uint32_t)(ks * 32);
            uint32_t af[4][4];
            #pragma unroll
            for (int mt = 0; mt < 4; mt++)
                LDSM_X4(af[mt][0], af[mt][1], af[mt][2], af[mt][3],
                        aLd + (uint32_t)(mt * 16 * ROWB) + kOff);
            uint32_t bf[4][2];
            #pragma unroll
            for (int nt = 0; nt < 4; nt++)
                LDSM_X2(bf[nt][0], bf[nt][1],
                        bLd + (uint32_t)(nt * 8 * ROWB) + kOff);
            #pragma unroll
            for (int mt = 0; mt < 4; mt++)
                #pragma unroll
                for (int nt = 0; nt < 4; nt++)
                    mma_f16(acc[mt][nt], af[mt], bf[nt]);
        }
        if (++cs == STAGES) cs = 0;
    }

    #pragma unroll
    for (int mt = 0; mt < 4; mt++) {
        int m0 = bm + wm * 64 + mt * 16 + g;
        int m1 = m0 + 8;
        #pragma unroll
        for (int nt = 0; nt < 4; nt++) {
            int n = bn + wn * 32 + nt * 8 + 2 * tg;
            float2 bz = *reinterpret_cast<const float2*>(bias + n);
            float2 o0, o1;
            o0.x = acc[mt][nt][0] + bz.x; o0.y = acc[mt][nt][1] + bz.y;
            o1.x = acc[mt][nt][2] + bz.x; o1.y = acc[mt][nt][3] + bz.y;
            if (ACT == 1) {
                o0.x = gelu_f(o0.x); o0.y = gelu_f(o0.y);
                o1.x = gelu_f(o1.x); o1.y = gelu_f(o1.y);
            }
            if (OUTH) {
                __half* Ch = (__half*)Cv;
                __half2 h0 = __floats2half2_rn(o0.x, o0.y);
                __half2 h1 = __floats2half2_rn(o1.x, o1.y);
                *reinterpret_cast<__half2*>(&Ch[(size_t)m0 * N + n]) = h0;
                *reinterpret_cast<__half2*>(&Ch[(size_t)m1 * N + n]) = h1;
            } else {
                float* C = (float*)Cv;
                *reinterpret_cast<float2*>(&C[(size_t)m0 * N + n]) = o0;
                *reinterpret_cast<float2*>(&C[(size_t)m1 * N + n]) = o1;
            }
        }
    }
}

// ---------------- LayerNorm (compacted): one WARP per row ----------------
__global__ void ln_k(const float* __restrict__ gam, const float* __restrict__ bet)
{
    const int wid = threadIdx.x >> 5, lane = threadIdx.x & 31;
    const int r = blockIdx.x * 8 + wid;
    if (r >= g_cnt) return;
    const float* x = &g_h2c[(size_t)r * 256 + lane * 8];
    float4 v0 = *reinterpret_cast<const float4*>(x);
    float4 v1 = *reinterpret_cast<const float4*>(x + 4);
    float s = v0.x+v0.y+v0.z+v0.w + v1.x+v1.y+v1.z+v1.w;
    #pragma unroll
    for (int o = 16; o > 0; o >>= 1) s += __shfl_xor_sync(0xffffffffu, s, o);
    float mu = s * (1.0f / 256.0f);
    float d0x=v0.x-mu, d0y=v0.y-mu, d0z=v0.z-mu, d0w=v0.w-mu;
    float d1x=v1.x-mu, d1y=v1.y-mu, d1z=v1.z-mu, d1w=v1.w-mu;
    float sq = d0x*d0x+d0y*d0y+d0z*d0z+d0w*d0w + d1x*d1x+d1y*d1y+d1z*d1z+d1w*d1w;
    #pragma unroll
    for (int o = 16; o > 0; o >>= 1) sq += __shfl_xor_sync(0xffffffffu, sq, o);
    float rs = rsqrtf(sq * (1.0f / 256.0f) + 1e-5f);
    float4 ga0 = *reinterpret_cast<const float4*>(gam + lane * 8);
    float4 ga1 = *reinterpret_cast<const float4*>(gam + lane * 8 + 4);
    float4 be0 = *reinterpret_cast<const float4*>(bet + lane * 8);
    float4 be1 = *reinterpret_cast<const float4*>(bet + lane * 8 + 4);
    float4 o0, o1;
    o0.x = d0x*rs*ga0.x + be0.x; o0.y = d0y*rs*ga0.y + be0.y;
    o0.z = d0z*rs*ga0.z + be0.z; o0.w = d0w*rs*ga0.w + be0.w;
    o1.x = d1x*rs*ga1.x + be1.x; o1.y = d1y*rs*ga1.y + be1.y;
    o1.z = d1z*rs*ga1.z + be1.z; o1.w = d1w*rs*ga1.w + be1.w;
    float* y = &g_redc[(size_t)r * 256 + lane * 8];
    *reinterpret_cast<float4*>(y)     = o0;
    *reinterpret_cast<float4*>(y + 4) = o1;
    __half2 h0 = __floats2half2_rn(o0.x, o0.y);
    __half2 h1 = __floats2half2_rn(o0.z, o0.w);
    __half2 h2 = __floats2half2_rn(o1.x, o1.y);
    __half2 h3 = __floats2half2_rn(o1.z, o1.w);
    uint4 hv;
    hv.x = *reinterpret_cast<uint32_t*>(&h0);
    hv.y = *reinterpret_cast<uint32_t*>(&h1);
    hv.z = *reinterpret_cast<uint32_t*>(&h2);
    hv.w = *reinterpret_cast<uint32_t*>(&h3);
    *reinterpret_cast<uint4*>(&g_redch[(size_t)r * 256 + lane * 8]) = hv;
}

// ---------------- attention: block per batch, warp per head, only use-rows ----------------
__global__ void attn_k(const int* __restrict__ mask)
{
    int b = blockIdx.x, tid = threadIdx.x;
    int h = tid >> 5, lane = tid & 31;
    __shared__ float qs[Hsz][Ssz][33], ks[Hsz][Ssz][33], vs[Hsz][Ssz][33];
    __shared__ float sc[Hsz][Ssz][Ssz + 1];
    __shared__ int exS[Ssz], useS[Ssz], idxS[Ssz], midS[Ssz];

    if (b == 0 && tid == 0) g_acc = 0.0f;
    if (tid < Ssz) {
        int r = b * Ssz + tid;
        exS[tid]  = (mask[r] > 0);
        useS[tid] = g_use[r];
        idxS[tid] = g_r2c[r];
        midS[tid] = g_use[r] ? g_m2c[r] : 0;
    }
    __syncthreads();
    if (!g_any[b]) return;     // no existing sections: all rows keep red

    #pragma unroll
    for (int s = 0; s < Ssz; s++) {
        size_t base = (size_t)idxS[s] * REDsz + h * DHsz + lane;
        ks[h][s][lane] = g_kc[base];
        vs[h][s][lane] = g_vc[base];
        if (useS[s]) qs[h][s][lane] = g_qc[base];
    }
    __syncwarp();

    for (int idx = lane; idx < Ssz * Ssz; idx += 32) {
        int i = idx / Ssz, j = idx - i * Ssz;
        if (!useS[i]) continue;
        float dot = 0.0f;
        #pragma unroll
        for (int d = 0; d < 32; d++) dot += qs[h][i][d] * ks[h][j][d];
        sc[h][i][j] = exS[j] ? dot * 0.17677669529663687f : -1e9f;
    }
    __syncwarp();

    if (lane < Ssz && useS[lane]) {
        int i = lane;
        float m = -1e30f;
        #pragma unroll
        for (int j = 0; j < Ssz; j++) m = fmaxf(m, sc[h][i][j]);
        float sum = 0.0f;
        #pragma unroll
        for (int j = 0; j < Ssz; j++) { float e = expf(sc[h][i][j] - m); sc[h][i][j] = e; sum += e; }
        float inv = 1.0f / sum;
        #pragma unroll
        for (int j = 0; j < Ssz; j++) sc[h][i][j] *= inv;
    }
    __syncwarp();

    #pragma unroll
    for (int i = 0; i < Ssz; i++) {
        if (!useS[i]) continue;
        float s = 0.0f;
        #pragma unroll
        for (int j = 0; j < Ssz; j++) s += sc[h][i][j] * vs[h][j][lane];
        g_ctxc[(size_t)midS[i] * REDsz + h * DHsz + lane] = __float2half_rn(s);
    }
}

// ---------------- merged orthogonality loss + logits (gathered X) ----------------
__global__ void losslogit_k(const float* __restrict__ Wp, const float* __restrict__ bp,
                            float* __restrict__ out, int loff)
{
    int b = blockIdx.x, tid = threadIdx.x;
    __shared__ float X[Ssz][REDsz + 1];
    __shared__ float inv[Ssz];
    __shared__ float mean[REDsz];
    __shared__ const float* srcS[Ssz];
    if (tid < Ssz) {
        int r = b * Ssz + tid;
        srcS[tid] = g_use[r] ? &g_updc[(size_t)g_m2c[r] * 256]
                             : &g_redc[(size_t)g_r2c[r] * 256];
    }
    __syncthreads();
    for (int idx = tid; idx < Ssz * REDsz; idx += 256) {
        int s = idx >> 8, d = idx & 255;
        X[s][d] = srcS[s][d];
    }
    __syncthreads();
    int w = tid >> 5, lane = tid & 31;
    for (int r = w; r < Ssz; r += 8) {
        float s = 0.0f;
        for (int d = lane; d < 256; d += 32) s += X[r][d] * X[r][d];
        for (int o = 16; o > 0; o >>= 1) s += __shfl_down_sync(0xffffffffu, s, o);
        if (lane == 0) inv[r] = 1.0f / fmaxf(sqrtf(s), 1e-8f);
    }
    {
        float s = 0.0f;
        #pragma unroll
        for (int ss = 0; ss < Ssz; ss++) s += X[ss][tid];
        mean[tid] = s * (1.0f / (float)Ssz);
    }
    __syncthreads();
    float part = 0.0f;
    if (tid < (Ssz * (Ssz - 1)) / 2) {
        int p = tid, i = 0;
        while (p >= Ssz - 1 - i) { p -= Ssz - 1 - i; i++; }
        int j = i + 1 + p;
        float dot = 0.0f;
        for (int d = 0; d < 256; d++) dot += X[i][d] * X[j][d];
        float gv = fabsf(dot * inv[i] * inv[j]);
        part = fmaxf(gv - 0.1f, 0.0f) * 2.0f;
    }
    __shared__ float red[256];
    red[tid] = part; __syncthreads();
    for (int s = 128; s > 0; s >>= 1) { if (tid < s) red[tid] += red[tid + s]; __syncthreads(); }
    if (tid == 0) atomicAdd(&g_acc, red[0]);
    if (tid < NLAB) {
        float a = bp[tid];
        const float* wr = Wp + tid * REDsz;
        for (int d = 0; d < REDsz; d++) a += mean[d] * wr[d];
        out[loff + b * NLAB + tid] = a;
    }
}

__global__ void fin_k(float* out, int writeloss)
{
    if (writeloss)
        out[0] = g_acc * (1.0f / ((float)Bsz * Ssz * (Ssz - 1)));
}

// ---------------- launch ----------------
extern "C" void kernel_launch(void* const* d_in, const int* in_sizes, int n_in,
                              void* d_out, int out_size)
{
    const float* cls  = (const float*)d_in[0];
    const int*   mask = (const int*)  d_in[1];
    const float* miss = (const float*)d_in[2];
    const float* W1 = (const float*)d_in[3];  const float* b1 = (const float*)d_in[4];
    const float* W2 = (const float*)d_in[5];  const float* b2 = (const float*)d_in[6];
    const float* lg = (const float*)d_in[7];  const float* lb = (const float*)d_in[8];
    const float* Wq = (const float*)d_in[9];  const float* bq = (const float*)d_in[10];
    const float* Wk = (const float*)d_in[11]; const float* bk = (const float*)d_in[12];
    const float* Wv = (const float*)d_in[13]; const float* bv = (const float*)d_in[14];
    const float* Wo = (const float*)d_in[15]; const float* bo = (const float*)d_in[16];
    const float* Wp = (const float*)d_in[17]; const float* bp = (const float*)d_in[18];
    float* out = (float*)d_out;

    int loff = out_size - Bsz * NLAB;
    if (loff < 0) loff = 0;

    __half *ac, *h1c, *redch, *ctxc, *wh;
    float *h2c, *qc, *kc, *vc, *updc;
    cudaGetSymbolAddress((void**)&ac,    g_ac);
    cudaGetSymbolAddress((void**)&h1c,   g_h1c);
    cudaGetSymbolAddress((void**)&h2c,   g_h2c);
    cudaGetSymbolAddress((void**)&redch, g_redch);
    cudaGetSymbolAddress((void**)&qc,    g_qc);
    cudaGetSymbolAddress((void**)&kc,    g_kc);
    cudaGetSymbolAddress((void**)&vc,    g_vc);
    cudaGetSymbolAddress((void**)&ctxc,  g_ctxc);
    cudaGetSymbolAddress((void**)&updc,  g_updc);
    cudaGetSymbolAddress((void**)&wh,    g_wh);

    cudaFuncSetAttribute(mmagemm_k<1,0,1,1>, cudaFuncAttributeMaxDynamicSharedMemorySize, SMEM_DYN);
    cudaFuncSetAttribute(mmagemm_k<1,0,0,1>, cudaFuncAttributeMaxDynamicSharedMemorySize, SMEM_DYN);
    cudaFuncSetAttribute(mmagemm_k<0,3,0,1>, cudaFuncAttributeMaxDynamicSharedMemorySize, SMEM_DYN);
    cudaFuncSetAttribute(mmagemm_k<0,0,0,2>, cudaFuncAttributeMaxDynamicSharedMemorySize, SMEM_DYN);

    dim3 blk(256);
    // 0) prep: any_exist + counters, compaction maps, gathered fp16 A, fp16 weights
    prep_k<<<(Bsz + 255) / 256, 256>>>(mask);
    assign_k<<<(Mrows + 255) / 256, 256>>>(mask);
    acopy_k<<<(((Mrows + Ssz) * (Esz / 8)) + 255) / 256, 256>>>(cls, miss, mask);
    wprep_k<<<(WTOT + 255) / 256, 256>>>(W1, W2, Wq, Wk, Wv, Wo);
    // 1) GEMM1 + GELU (compacted) -> fp16 h1c
    mmagemm_k<1,0,1,1><<<dim3(3, MCtiles), blk, SMEM_DYN>>>(
        ac, wh + OFF_W1, nullptr, nullptr, b1, nullptr, nullptr,
        h1c, nullptr, nullptr, 384, 768);
    // 2) GEMM2 + GELU (compacted) -> fp32 h2c
    mmagemm_k<1,0,0,1><<<dim3(2, MCtiles), blk, SMEM_DYN>>>(
        h1c, wh + OFF_W2, nullptr, nullptr, b2, nullptr, nullptr,
        h2c, nullptr, nullptr, 256, 384);
    // 3) LayerNorm (compacted) -> redc + redch
    ln_k<<<MCc / 8, 256>>>(lg, lb);
    // 4) fused QKV (compacted; q-branch only tile 0)
    mmagemm_k<0,3,0,1><<<dim3(6, MCtiles), blk, SMEM_DYN>>>(
        redch, wh + OFF_WQ, wh + OFF_WK, wh + OFF_WV, bq, bk, bv,
        qc, kc, vc, 256, 256);
    // 5) attention (only use-rows; writes compacted fp16 ctx)
    attn_k<<<Bsz, 256>>>(mask);
    // 6) Wo projection over missing rows only -> updc
    mmagemm_k<0,0,0,2><<<dim3(2, Mrows/128), blk, SMEM_DYN>>>(
        ctxc, wh + OFF_WO, nullptr, nullptr, bo, nullptr, nullptr,
        updc, nullptr, nullptr, 256, 256);
    // 7) merged orthogonality loss + logits (gathers updc/redc)
    losslogit_k<<<Bsz, 256>>>(Wp, bp, out, loff);
    // 8) finalize loss scalar
    fin_k<<<1, 1>>>(out, loff >= 1 ? 1 : 0);
}